// round 12
// baseline (speedup 1.0000x reference)
#include <cuda_runtime.h>
#include <cuda_bf16.h>
#include <cstdint>

// ---------------------------------------------------------------------------
// BotRGCN on GB300 — bf16 mma.sync (m16n8k16) pipeline.
//   rgcn(x) = [x | mean_0(x) | mean_1(x)] @ [W_root; W_rel0; W_rel1] + b
// R12: revert mainloop to R10 (BK=32, STR=40); split non-head GEMMs to BN=64
// tiles (32 acc regs/thread -> 3 CTAs/SM, 24 warps) to attack the measured
// latency-boundness (issue ~10%, occ ~24% at 2 CTAs/SM). Head GEMM stays
// BN=128 (epilogue needs all cols in-block).
// ---------------------------------------------------------------------------

#define MAXN 100000
#define MAXE 3200000
#define NRSEG (MAXN * 2)

__device__ __align__(256) __nv_bfloat16 g_A[(size_t)MAXN * 384];
__device__ __align__(256) __nv_bfloat16 g_B[(size_t)MAXN * 384];
__device__ __align__(256) __nv_bfloat16 g_Wt_des[32 * 768];
__device__ __align__(256) __nv_bfloat16 g_Wt_tweet[32 * 768];
__device__ __align__(256) __nv_bfloat16 g_Wt_prop[32 * 64];
__device__ __align__(256) __nv_bfloat16 g_Wt_in[128 * 128];
__device__ __align__(256) __nv_bfloat16 g_Wt_cat[128 * 384];
__device__ __align__(256) __nv_bfloat16 g_Wt_o1[128 * 128];
__device__ __align__(256) int g_perm[MAXE];
__device__ __align__(256) int g_seg_start[NRSEG];
// cnt | cursor | total : one contiguous region, zeroed by a single memset
__device__ __align__(256) int g_cntcur[2 * NRSEG + 1];

__device__ __forceinline__ uint32_t smem_u32(const void* p) {
    uint32_t a;
    asm("{ .reg .u64 t; cvta.to.shared.u64 t, %1; cvt.u32.u64 %0, t; }"
        : "=r"(a) : "l"(p));
    return a;
}

// ------------------------- segment offsets (unordered CSR) -----------------

__global__ void seg_offsets_kernel(const int* __restrict__ cnt,
                                   int* __restrict__ seg_start,
                                   int* __restrict__ total, int n) {
    __shared__ int s[1024];
    __shared__ int base;
    int idx = blockIdx.x * 1024 + threadIdx.x;
    int v = (idx < n) ? cnt[idx] : 0;
    s[threadIdx.x] = v;
    __syncthreads();
    for (int off = 1; off < 1024; off <<= 1) {
        int t = (threadIdx.x >= off) ? s[threadIdx.x - off] : 0;
        __syncthreads();
        s[threadIdx.x] += t;
        __syncthreads();
    }
    if (threadIdx.x == 1023) base = atomicAdd(total, s[1023]);
    __syncthreads();
    if (idx < n) seg_start[idx] = base + s[threadIdx.x] - v;
}

// ------------------------- Weight prep (single launch) ---------------------

__device__ __forceinline__ void tr_one(const float* in, __nv_bfloat16* out,
                                       int idx, int K, int Nw, int Kpad) {
    int n = idx / Kpad, k = idx % Kpad;
    out[idx] = (k < K) ? __float2bfloat16_rn(in[k * Nw + n])
                       : __float2bfloat16_rn(0.f);
}

#define PREP_TOTAL (24576 + 24576 + 2048 + 16384 + 16384 + 49152)

__global__ void prep_kernel(const float* __restrict__ W_des,
                            const float* __restrict__ W_tweet,
                            const float* __restrict__ W_prop,
                            const float* __restrict__ W_in,
                            const float* __restrict__ W_o1,
                            const float* __restrict__ W_root,
                            const float* __restrict__ W_rel,
                            __nv_bfloat16* __restrict__ Wt_des,
                            __nv_bfloat16* __restrict__ Wt_tweet,
                            __nv_bfloat16* __restrict__ Wt_prop,
                            __nv_bfloat16* __restrict__ Wt_in,
                            __nv_bfloat16* __restrict__ Wt_o1,
                            __nv_bfloat16* __restrict__ Wt_cat) {
    int idx = blockIdx.x * blockDim.x + threadIdx.x;
    if (idx < 24576) {
        tr_one(W_des, Wt_des, idx, 768, 32, 768);
    } else if ((idx -= 24576) < 24576) {
        tr_one(W_tweet, Wt_tweet, idx, 768, 32, 768);
    } else if ((idx -= 24576) < 2048) {
        tr_one(W_prop, Wt_prop, idx, 14, 32, 64);
    } else if ((idx -= 2048) < 16384) {
        tr_one(W_in, Wt_in, idx, 96, 128, 128);
    } else if ((idx -= 16384) < 16384) {
        tr_one(W_o1, Wt_o1, idx, 128, 128, 128);
    } else if ((idx -= 16384) < 49152) {
        int n = idx / 384, k = idx % 384;
        float v = (k < 128) ? W_root[k * 128 + n] : W_rel[(k - 128) * 128 + n];
        Wt_cat[idx] = __float2bfloat16_rn(v);
    }
}

// ------------------------- mma primitives ----------------------------------

#define LDMX4(r0, r1, r2, r3, addr)                                           \
    asm volatile("ldmatrix.sync.aligned.m8n8.x4.shared.b16 {%0,%1,%2,%3}, [%4];" \
                 : "=r"(r0), "=r"(r1), "=r"(r2), "=r"(r3) : "r"(addr))
#define LDMX2(r0, r1, addr)                                                   \
    asm volatile("ldmatrix.sync.aligned.m8n8.x2.shared.b16 {%0,%1}, [%2];"    \
                 : "=r"(r0), "=r"(r1) : "r"(addr))
#define MMA16816(c, a, b)                                                     \
    asm volatile(                                                             \
        "mma.sync.aligned.m16n8k16.row.col.f32.bf16.bf16.f32 "                \
        "{%0,%1,%2,%3}, {%4,%5,%6,%7}, {%8,%9}, {%0,%1,%2,%3};"               \
        : "+f"((c)[0]), "+f"((c)[1]), "+f"((c)[2]), "+f"((c)[3])              \
        : "r"((a)[0]), "r"((a)[1]), "r"((a)[2]), "r"((a)[3]),                 \
          "r"((b)[0]), "r"((b)[1]))

// ------------------------- fused encoder GEMM + edge count ------------------
// Blocks [0, ncnt): CSR count (grid-stride histogram).
// Blocks [ncnt, ncnt + 3*gm): encoder slices (des | tweet | prop).

__global__ void __launch_bounds__(128) gemm_enc3_count(
    const float* __restrict__ des, const float* __restrict__ tweet,
    const float* __restrict__ prop,
    const __nv_bfloat16* __restrict__ Wt_des,
    const __nv_bfloat16* __restrict__ Wt_tweet,
    const __nv_bfloat16* __restrict__ Wt_prop,
    const float* __restrict__ b_des, const float* __restrict__ b_tweet,
    const float* __restrict__ b_prop, __nv_bfloat16* __restrict__ Bout,
    int M, int gm,
    const int* __restrict__ dstE, const int* __restrict__ etE, int E,
    int* __restrict__ cnt, int ncnt) {
    if (blockIdx.x < (unsigned)ncnt) {
        for (int i = blockIdx.x * 128 + threadIdx.x; i < E; i += ncnt * 128)
            atomicAdd(&cnt[dstE[i] * 2 + etE[i]], 1);
        return;
    }
    const int flat = blockIdx.x - ncnt;
    const int bx = flat % gm, by = flat / gm;

    const float* A;
    const __nv_bfloat16* Wt;
    const float* bias;
    __nv_bfloat16* C;
    int lda, K, ldw;
    if (by == 0) {
        A = des; Wt = Wt_des; bias = b_des; C = Bout; lda = 768; K = 768; ldw = 768;
    } else if (by == 1) {
        A = tweet; Wt = Wt_tweet; bias = b_tweet; C = Bout + 32; lda = 768; K = 768; ldw = 768;
    } else {
        A = prop; Wt = Wt_prop; bias = b_prop; C = Bout + 64; lda = 14; K = 14; ldw = 64;
    }
    const int ldc = 384;

    constexpr int STR = 40;
    __shared__ __nv_bfloat16 sA[128 * STR];
    __shared__ __nv_bfloat16 sB[32 * STR];

    const int tid = threadIdx.x;
    const int wid = tid >> 5, lane = tid & 31;
    const int row0 = bx * 128;
    const uint32_t baseA = smem_u32(sA);
    const uint32_t baseB = smem_u32(sB);

    float acc[2][4][4];
#pragma unroll
    for (int i = 0; i < 2; i++)
#pragma unroll
        for (int j = 0; j < 4; j++)
#pragma unroll
            for (int q = 0; q < 4; q++) acc[i][j][q] = 0.f;

    uint32_t aAddr[2];
#pragma unroll
    for (int i = 0; i < 2; i++)
        aAddr[i] = baseA + (uint32_t)(((wid * 32 + i * 16 + (lane & 15)) * STR +
                                       ((lane >> 4) * 8)) * 2);
    uint32_t bAddr[4];
#pragma unroll
    for (int j = 0; j < 4; j++)
        bAddr[j] = baseB + (uint32_t)(((j * 8 + (lane & 7)) * STR +
                                       (((lane >> 3) & 1) * 8)) * 2);

    const int nchunks = (K + 31) >> 5;
    for (int c = 0; c < nchunks; c++) {
        const int k0 = c << 5;
#pragma unroll 2
        for (int idx = tid; idx < 128 * 4; idx += 128) {
            int r = idx >> 2, g = idx & 3;
            int gr = row0 + r, gc0 = k0 + g * 8;
            uint4 val;
            if (gr < M && gc0 + 7 < K && (lda & 3) == 0) {
                const float4* p = (const float4*)(A + (size_t)gr * lda + gc0);
                float4 v0 = p[0], v1 = p[1];
                __nv_bfloat162 h0 = __floats2bfloat162_rn(v0.x, v0.y);
                __nv_bfloat162 h1 = __floats2bfloat162_rn(v0.z, v0.w);
                __nv_bfloat162 h2 = __floats2bfloat162_rn(v1.x, v1.y);
                __nv_bfloat162 h3 = __floats2bfloat162_rn(v1.z, v1.w);
                val.x = *(uint32_t*)&h0; val.y = *(uint32_t*)&h1;
                val.z = *(uint32_t*)&h2; val.w = *(uint32_t*)&h3;
            } else {
                float v[8];
#pragma unroll
                for (int e = 0; e < 8; e++) {
                    int gc = gc0 + e;
                    v[e] = (gr < M && gc < K) ? A[(size_t)gr * lda + gc] : 0.f;
                }
                __nv_bfloat162 h0 = __floats2bfloat162_rn(v[0], v[1]);
                __nv_bfloat162 h1 = __floats2bfloat162_rn(v[2], v[3]);
                __nv_bfloat162 h2 = __floats2bfloat162_rn(v[4], v[5]);
                __nv_bfloat162 h3 = __floats2bfloat162_rn(v[6], v[7]);
                val.x = *(uint32_t*)&h0; val.y = *(uint32_t*)&h1;
                val.z = *(uint32_t*)&h2; val.w = *(uint32_t*)&h3;
            }
            *(uint4*)(sA + r * STR + g * 8) = val;
        }
        {
            int n = tid >> 2, g = tid & 3;
            uint4 val = *(const uint4*)(Wt + (size_t)n * ldw + k0 + g * 8);
            *(uint4*)(sB + n * STR + g * 8) = val;
        }
        __syncthreads();

#pragma unroll
        for (int s = 0; s < 2; s++) {
            uint32_t bfr[4][2];
#pragma unroll
            for (int j = 0; j < 4; j++)
                LDMX2(bfr[j][0], bfr[j][1], bAddr[j] + s * 32);
#pragma unroll
            for (int i = 0; i < 2; i++) {
                uint32_t afr[4];
                LDMX4(afr[0], afr[1], afr[2], afr[3], aAddr[i] + s * 32);
#pragma unroll
                for (int j = 0; j < 4; j++) MMA16816(acc[i][j], afr, bfr[j]);
            }
        }
        __syncthreads();
    }

    const int qrow = lane >> 2, qcol = (lane & 3) * 2;
#pragma unroll
    for (int i = 0; i < 2; i++) {
#pragma unroll
        for (int j = 0; j < 4; j++) {
            int gc = j * 8 + qcol;
            float b0 = bias[gc], b1 = bias[gc + 1];
            int gr0 = row0 + wid * 32 + i * 16 + qrow;
            float v0 = acc[i][j][0] + b0, v1 = acc[i][j][1] + b1;
            float v2 = acc[i][j][2] + b0, v3 = acc[i][j][3] + b1;
            v0 = (v0 >= 0.f) ? v0 : 0.01f * v0;
            v1 = (v1 >= 0.f) ? v1 : 0.01f * v1;
            v2 = (v2 >= 0.f) ? v2 : 0.01f * v2;
            v3 = (v3 >= 0.f) ? v3 : 0.01f * v3;
            if (gr0 < M) {
                __nv_bfloat162 h = __floats2bfloat162_rn(v0, v1);
                *(uint32_t*)(C + (size_t)gr0 * ldc + gc) = *(uint32_t*)&h;
            }
            if (gr0 + 8 < M) {
                __nv_bfloat162 h = __floats2bfloat162_rn(v2, v3);
                *(uint32_t*)(C + (size_t)(gr0 + 8) * ldc + gc) = *(uint32_t*)&h;
            }
        }
    }
}

// ------------------------- main GEMM (bf16 A, R10 mainloop) ----------------
// C[M, BNT](bf16, ldc) = act( A[M,K](bf16) @ Wt'[BNT,K]^T + bias' )
// BM=128, BK=32, 256 threads, 8 warps (4 x 2), warp tile 32 x (BNT/2).
// BNT=64: 32 acc regs/thread, minctasm=3 -> 24 warps/SM (latency fix).
// BNT=128 (HEAD only): R10 footprint, softmax epilogue -> fp32 [M,2].
// PLACE: blocks [0, nplace) run CSR place instead (fused independent work).

template <int BNT, bool HEAD, bool PLACE>
__global__ void __launch_bounds__(256, BNT == 64 ? 3 : 1) gemm_mma(
    const __nv_bfloat16* __restrict__ Aptr, int lda,
    const __nv_bfloat16* __restrict__ Wt, int ldw,
    const float* __restrict__ bias, __nv_bfloat16* __restrict__ C, int ldc,
    int M, int K, int act, int gm,
    const float* __restrict__ W_o2, const float* __restrict__ b_o2,
    float* __restrict__ outp,
    const int* __restrict__ srcE, const int* __restrict__ dstE,
    const int* __restrict__ etE, int E, const int* __restrict__ seg_start,
    int* __restrict__ cursor, int* __restrict__ perm, int nplace) {
    if (PLACE) {
        if (blockIdx.x < (unsigned)nplace) {
            for (int i = blockIdx.x * 256 + threadIdx.x; i < E;
                 i += nplace * 256) {
                int seg = dstE[i] * 2 + etE[i];
                int p = atomicAdd(&cursor[seg], 1);
                perm[seg_start[seg] + p] = srcE[i];
            }
            return;
        }
    }
    const int bx = PLACE ? (blockIdx.x - nplace) : blockIdx.x;
    const int bxm = bx % gm;              // row-tile index
    const int col0 = (bx / gm) * BNT;     // column-slice offset (0 for BNT=128)

    constexpr int THREADS = 256;
    constexpr int WN = BNT / 2;           // 32 or 64
    constexpr int NATOMS = WN / 8;        // 4 or 8
    constexpr int STR = 40;

    const __nv_bfloat16* Wtp = Wt + (size_t)col0 * ldw;
    const float* biasp = bias + col0;

    __shared__ __nv_bfloat16 sA[128 * STR];
    __shared__ __nv_bfloat16 sB[BNT * STR];

    const int tid = threadIdx.x;
    const int wid = tid >> 5, lane = tid & 31;
    const int wm = wid & 3, wn = wid >> 2;
    const int row0 = bxm * 128;
    const uint32_t baseA = smem_u32(sA);
    const uint32_t baseB = smem_u32(sB);

    float acc[2][NATOMS][4];
#pragma unroll
    for (int i = 0; i < 2; i++)
#pragma unroll
        for (int j = 0; j < NATOMS; j++)
#pragma unroll
            for (int q = 0; q < 4; q++) acc[i][j][q] = 0.f;

    uint32_t aAddr[2];
#pragma unroll
    for (int i = 0; i < 2; i++)
        aAddr[i] = baseA + (uint32_t)(((wm * 32 + i * 16 + (lane & 15)) * STR +
                                       ((lane >> 4) * 8)) * 2);
    uint32_t bAddr[NATOMS];
#pragma unroll
    for (int j = 0; j < NATOMS; j++)
        bAddr[j] = baseB + (uint32_t)(((wn * WN + j * 8 + (lane & 7)) * STR +
                                       (((lane >> 3) & 1) * 8)) * 2);

    const int nchunks = (K + 31) >> 5;
    for (int c = 0; c < nchunks; c++) {
        const int k0 = c << 5;
#pragma unroll 2
        for (int idx = tid; idx < 128 * 4; idx += THREADS) {
            int r = idx >> 2, g = idx & 3;
            int gr = row0 + r;
            uint4 val = (gr < M)
                            ? *(const uint4*)(Aptr + (size_t)gr * lda + k0 + g * 8)
                            : make_uint4(0, 0, 0, 0);
            *(uint4*)(sA + r * STR + g * 8) = val;
        }
#pragma unroll
        for (int idx = tid; idx < BNT * 4; idx += THREADS) {
            int n = idx >> 2, g = idx & 3;
            uint4 val = *(const uint4*)(Wtp + (size_t)n * ldw + k0 + g * 8);
            *(uint4*)(sB + n * STR + g * 8) = val;
        }
        __syncthreads();

        if (c + 1 < nchunks) {
            int r = tid >> 1;
            if ((tid & 1) == 0) {
                int gr = row0 + r;
                if (gr < M) {
                    const void* p = (const void*)(Aptr + (size_t)gr * lda +
                                                  ((c + 1) << 5));
                    asm volatile("prefetch.global.L2 [%0];" :: "l"(p));
                }
            }
        }

#pragma unroll
        for (int s = 0; s < 2; s++) {
            uint32_t bfr[NATOMS][2];
#pragma unroll
            for (int j = 0; j < NATOMS; j++)
                LDMX2(bfr[j][0], bfr[j][1], bAddr[j] + s * 32);
#pragma unroll
            for (int i = 0; i < 2; i++) {
                uint32_t afr[4];
                LDMX4(afr[0], afr[1], afr[2], afr[3], aAddr[i] + s * 32);
#pragma unroll
                for (int j = 0; j < NATOMS; j++) MMA16816(acc[i][j], afr, bfr[j]);
            }
        }
        __syncthreads();
    }

    const int qrow = lane >> 2, qcol = (lane & 3) * 2;

    if (!HEAD) {
#pragma unroll
        for (int i = 0; i < 2; i++) {
#pragma unroll
            for (int j = 0; j < NATOMS; j++) {
                int gc = wn * WN + j * 8 + qcol;
                float b0 = biasp[gc], b1 = biasp[gc + 1];
                int gr0 = row0 + wm * 32 + i * 16 + qrow;
                float v0 = acc[i][j][0] + b0, v1 = acc[i][j][1] + b1;
                float v2 = acc[i][j][2] + b0, v3 = acc[i][j][3] + b1;
                if (act) {
                    v0 = (v0 >= 0.f) ? v0 : 0.01f * v0;
                    v1 = (v1 >= 0.f) ? v1 : 0.01f * v1;
                    v2 = (v2 >= 0.f) ? v2 : 0.01f * v2;
                    v3 = (v3 >= 0.f) ? v3 : 0.01f * v3;
                }
                if (gr0 < M) {
                    __nv_bfloat162 h = __floats2bfloat162_rn(v0, v1);
                    *(uint32_t*)(C + (size_t)gr0 * ldc + col0 + gc) = *(uint32_t*)&h;
                }
                if (gr0 + 8 < M) {
                    __nv_bfloat162 h = __floats2bfloat162_rn(v2, v3);
                    *(uint32_t*)(C + (size_t)(gr0 + 8) * ldc + col0 + gc) = *(uint32_t*)&h;
                }
            }
        }
    } else {
        __shared__ float sred[2][128][2];
        float p0[4] = {0.f, 0.f, 0.f, 0.f};
        float p1[4] = {0.f, 0.f, 0.f, 0.f};
#pragma unroll
        for (int i = 0; i < 2; i++) {
#pragma unroll
            for (int j = 0; j < NATOMS; j++) {
                int gc = wn * WN + j * 8 + qcol;
                float b0 = biasp[gc], b1 = biasp[gc + 1];
                float v0 = acc[i][j][0] + b0, v1 = acc[i][j][1] + b1;
                float v2 = acc[i][j][2] + b0, v3 = acc[i][j][3] + b1;
                v0 = (v0 >= 0.f) ? v0 : 0.01f * v0;
                v1 = (v1 >= 0.f) ? v1 : 0.01f * v1;
                v2 = (v2 >= 0.f) ? v2 : 0.01f * v2;
                v3 = (v3 >= 0.f) ? v3 : 0.01f * v3;
                float w00 = W_o2[gc * 2], w01 = W_o2[gc * 2 + 1];
                float w10 = W_o2[(gc + 1) * 2], w11 = W_o2[(gc + 1) * 2 + 1];
                p0[i * 2 + 0] += v0 * w00 + v1 * w10;
                p1[i * 2 + 0] += v0 * w01 + v1 * w11;
                p0[i * 2 + 1] += v2 * w00 + v3 * w10;
                p1[i * 2 + 1] += v2 * w01 + v3 * w11;
            }
        }
#pragma unroll
        for (int off = 1; off <= 2; off <<= 1) {
#pragma unroll
            for (int k = 0; k < 4; k++) {
                p0[k] += __shfl_xor_sync(0xFFFFFFFFu, p0[k], off);
                p1[k] += __shfl_xor_sync(0xFFFFFFFFu, p1[k], off);
            }
        }
        if ((lane & 3) == 0) {
#pragma unroll
            for (int k = 0; k < 4; k++) {
                int row = wm * 32 + (k >> 1) * 16 + qrow + (k & 1) * 8;
                sred[wn][row][0] = p0[k];
                sred[wn][row][1] = p1[k];
            }
        }
        __syncthreads();
        if (tid < 128) {
            int gr = row0 + tid;
            if (gr < M) {
                float l0 = b_o2[0] + sred[0][tid][0] + sred[1][tid][0];
                float l1 = b_o2[1] + sred[0][tid][1] + sred[1][tid][1];
                float m = fmaxf(l0, l1);
                float e0 = __expf(l0 - m), e1 = __expf(l1 - m);
                float inv = 1.f / (e0 + e1);
                outp[(size_t)gr * 2] = e0 * inv;
                outp[(size_t)gr * 2 + 1] = e1 * inv;
            }
        }
    }
}

// ------------------------- Aggregation (bf16, warp/segment) ----------------

__global__ void aggregate_kernel(__nv_bfloat16* __restrict__ buf,
                                 const int* __restrict__ seg_start,
                                 const int* __restrict__ cnt,
                                 const int* __restrict__ perm, int NR) {
    int w = blockIdx.x * (blockDim.x >> 5) + (threadIdx.x >> 5);
    if (w >= NR) return;
    int lane = threadIdx.x & 31;
    int start = seg_start[w];
    int deg = cnt[w];
    int end = start + deg;
    float a0 = 0.f, a1 = 0.f, a2 = 0.f, a3 = 0.f;
    int e = start;
    for (; e + 3 < end; e += 4) {
        int s0 = perm[e], s1 = perm[e + 1], s2 = perm[e + 2], s3 = perm[e + 3];
        uint2 v0 = *(const uint2*)(buf + (size_t)s0 * 384 + lane * 4);
        uint2 v1 = *(const uint2*)(buf + (size_t)s1 * 384 + lane * 4);
        uint2 v2 = *(const uint2*)(buf + (size_t)s2 * 384 + lane * 4);
        uint2 v3 = *(const uint2*)(buf + (size_t)s3 * 384 + lane * 4);
#define ACCUM(v)                                                              \
        {                                                                     \
            float2 f0 = __bfloat1622float2(*(__nv_bfloat162*)&(v).x);         \
            float2 f1 = __bfloat1622float2(*(__nv_bfloat162*)&(v).y);         \
            a0 += f0.x; a1 += f0.y; a2 += f1.x; a3 += f1.y;                   \
        }
        ACCUM(v0) ACCUM(v1) ACCUM(v2) ACCUM(v3)
    }
    for (; e < end; e++) {
        int s = perm[e];
        uint2 v = *(const uint2*)(buf + (size_t)s * 384 + lane * 4);
        ACCUM(v)
    }
#undef ACCUM
    float inv = 1.f / (float)max(deg, 1);
    __nv_bfloat162 h0 = __floats2bfloat162_rn(a0 * inv, a1 * inv);
    __nv_bfloat162 h1 = __floats2bfloat162_rn(a2 * inv, a3 * inv);
    uint2 outv;
    outv.x = *(uint32_t*)&h0;
    outv.y = *(uint32_t*)&h1;
    int node = w >> 1, r = w & 1;
    *(uint2*)(buf + (size_t)node * 384 + 128 + r * 128 + lane * 4) = outv;
}

// ------------------------- Launch ------------------------------------------

extern "C" void kernel_launch(void* const* d_in, const int* in_sizes, int n_in,
                              void* d_out, int out_size) {
    const float* des     = (const float*)d_in[0];
    const float* tweet   = (const float*)d_in[1];
    const float* prop    = (const float*)d_in[2];
    const int*   eidx    = (const int*)d_in[3];
    const int*   etype   = (const int*)d_in[4];
    const float* W_des   = (const float*)d_in[5];
    const float* b_des   = (const float*)d_in[6];
    const float* W_tweet = (const float*)d_in[7];
    const float* b_tweet = (const float*)d_in[8];
    const float* W_prop  = (const float*)d_in[9];
    const float* b_prop  = (const float*)d_in[10];
    const float* W_in    = (const float*)d_in[11];
    const float* b_in    = (const float*)d_in[12];
    const float* W_rel   = (const float*)d_in[13];
    const float* W_root  = (const float*)d_in[14];
    const float* b_rgcn  = (const float*)d_in[15];
    const float* W_o1    = (const float*)d_in[16];
    const float* b_o1    = (const float*)d_in[17];
    const float* W_o2    = (const float*)d_in[18];
    const float* b_o2    = (const float*)d_in[19];

    const int N = in_sizes[0] / 768;
    const int E = in_sizes[4];
    const int NR = N * 2;
    const int* src = eidx;
    const int* dst = eidx + E;

    __nv_bfloat16 *A, *B, *Wt_des, *Wt_tweet, *Wt_prop, *Wt_in, *Wt_cat, *Wt_o1;
    cudaGetSymbolAddress((void**)&A, g_A);
    cudaGetSymbolAddress((void**)&B, g_B);
    cudaGetSymbolAddress((void**)&Wt_des, g_Wt_des);
    cudaGetSymbolAddress((void**)&Wt_tweet, g_Wt_tweet);
    cudaGetSymbolAddress((void**)&Wt_prop, g_Wt_prop);
    cudaGetSymbolAddress((void**)&Wt_in, g_Wt_in);
    cudaGetSymbolAddress((void**)&Wt_cat, g_Wt_cat);
    cudaGetSymbolAddress((void**)&Wt_o1, g_Wt_o1);
    int *perm, *seg_start, *cntcur;
    cudaGetSymbolAddress((void**)&perm, g_perm);
    cudaGetSymbolAddress((void**)&seg_start, g_seg_start);
    cudaGetSymbolAddress((void**)&cntcur, g_cntcur);
    int* cnt = cntcur;
    int* cursor = cntcur + NRSEG;
    int* total = cntcur + 2 * NRSEG;

    const int gm = (N + 127) / 128;
    const int ncnt = 2048;
    const int nplace = 1024;

    // launch 1: zero cnt + cursor + total in one memset
    cudaMemsetAsync(cntcur, 0, (size_t)(2 * NRSEG + 1) * sizeof(int));
    // launch 2: weight prep
    prep_kernel<<<(PREP_TOTAL + 255) / 256, 256>>>(
        W_des, W_tweet, W_prop, W_in, W_o1, W_root, W_rel, Wt_des, Wt_tweet,
        Wt_prop, Wt_in, Wt_o1, Wt_cat);
    // launch 3: encoders + CSR count
    gemm_enc3_count<<<ncnt + gm * 3, 128>>>(des, tweet, prop, Wt_des, Wt_tweet,
                                            Wt_prop, b_des, b_tweet, b_prop, B,
                                            N, gm, dst, etype, E, cnt, ncnt);
    // launch 4: segment offsets (unordered CSR)
    seg_offsets_kernel<<<(NR + 1023) / 1024, 1024>>>(cnt, seg_start, total, NR);
    // launch 5: cat96 @ W_in -> A cols 0..127 (BN=64 x2) + CSR place
    gemm_mma<64, false, true><<<nplace + gm * 2, 256>>>(
        B, 384, Wt_in, 128, b_in, A, 384, N, 96, 1, gm, nullptr, nullptr,
        nullptr, src, dst, etype, E, seg_start, cursor, perm, nplace);
    // launch 6: aggregate layer 1
    aggregate_kernel<<<(NR + 7) / 8, 256>>>(A, seg_start, cnt, perm, NR);
    // launch 7: rgcn layer 1 GEMM (BN=64 x2)
    gemm_mma<64, false, false><<<gm * 2, 256>>>(
        A, 384, Wt_cat, 384, b_rgcn, B, 384, N, 384, 0, gm, nullptr, nullptr,
        nullptr, nullptr, nullptr, nullptr, 0, nullptr, nullptr, nullptr, 0);
    // launch 8: aggregate layer 2
    aggregate_kernel<<<(NR + 7) / 8, 256>>>(B, seg_start, cnt, perm, NR);
    // launch 9: rgcn layer 2 GEMM (BN=64 x2)
    gemm_mma<64, false, false><<<gm * 2, 256>>>(
        B, 384, Wt_cat, 384, b_rgcn, A, 384, N, 384, 0, gm, nullptr, nullptr,
        nullptr, nullptr, nullptr, nullptr, 0, nullptr, nullptr, nullptr, 0);
    // launch 10: head (BN=128, R10 footprint)
    gemm_mma<128, true, false><<<gm, 256>>>(
        A, 384, Wt_o1, 128, b_o1, nullptr, 384, N, 128, 1, gm, W_o2, b_o2,
        (float*)d_out, nullptr, nullptr, nullptr, 0, nullptr, nullptr,
        nullptr, 0);
}

// round 13
// speedup vs baseline: 1.4421x; 1.4421x over previous
#include <cuda_runtime.h>
#include <cuda_bf16.h>
#include <cstdint>

// ---------------------------------------------------------------------------
// BotRGCN on GB300 — bf16 mma.sync (m16n8k16) pipeline.
//   rgcn(x) = [x | mean_0(x) | mean_1(x)] @ [W_root; W_rel0; W_rel1] + b
// R13: exact R10 restore (best known 539.8us) for all GEMM/CSR/encoder code.
// One isolated change: aggregate_kernel processes 2 edges/warp/iter with
// uint4 loads (half-warp per edge), combining halves via shfl at the end.
// ---------------------------------------------------------------------------

#define MAXN 100000
#define MAXE 3200000
#define NRSEG (MAXN * 2)

__device__ __align__(256) __nv_bfloat16 g_A[(size_t)MAXN * 384];
__device__ __align__(256) __nv_bfloat16 g_B[(size_t)MAXN * 384];
__device__ __align__(256) __nv_bfloat16 g_Wt_des[32 * 768];
__device__ __align__(256) __nv_bfloat16 g_Wt_tweet[32 * 768];
__device__ __align__(256) __nv_bfloat16 g_Wt_prop[32 * 64];
__device__ __align__(256) __nv_bfloat16 g_Wt_in[128 * 128];
__device__ __align__(256) __nv_bfloat16 g_Wt_cat[128 * 384];
__device__ __align__(256) __nv_bfloat16 g_Wt_o1[128 * 128];
__device__ __align__(256) int g_perm[MAXE];
__device__ __align__(256) int g_seg_start[NRSEG];
// cnt | cursor | total : one contiguous region, zeroed by a single memset
__device__ __align__(256) int g_cntcur[2 * NRSEG + 1];

__device__ __forceinline__ uint32_t smem_u32(const void* p) {
    uint32_t a;
    asm("{ .reg .u64 t; cvta.to.shared.u64 t, %1; cvt.u32.u64 %0, t; }"
        : "=r"(a) : "l"(p));
    return a;
}

// ------------------------- segment offsets (unordered CSR) -----------------

__global__ void seg_offsets_kernel(const int* __restrict__ cnt,
                                   int* __restrict__ seg_start,
                                   int* __restrict__ total, int n) {
    __shared__ int s[1024];
    __shared__ int base;
    int idx = blockIdx.x * 1024 + threadIdx.x;
    int v = (idx < n) ? cnt[idx] : 0;
    s[threadIdx.x] = v;
    __syncthreads();
    for (int off = 1; off < 1024; off <<= 1) {
        int t = (threadIdx.x >= off) ? s[threadIdx.x - off] : 0;
        __syncthreads();
        s[threadIdx.x] += t;
        __syncthreads();
    }
    if (threadIdx.x == 1023) base = atomicAdd(total, s[1023]);
    __syncthreads();
    if (idx < n) seg_start[idx] = base + s[threadIdx.x] - v;
}

// ------------------------- Weight prep (single launch) ---------------------

__device__ __forceinline__ void tr_one(const float* in, __nv_bfloat16* out,
                                       int idx, int K, int Nw, int Kpad) {
    int n = idx / Kpad, k = idx % Kpad;
    out[idx] = (k < K) ? __float2bfloat16_rn(in[k * Nw + n])
                       : __float2bfloat16_rn(0.f);
}

#define PREP_TOTAL (24576 + 24576 + 2048 + 16384 + 16384 + 49152)

__global__ void prep_kernel(const float* __restrict__ W_des,
                            const float* __restrict__ W_tweet,
                            const float* __restrict__ W_prop,
                            const float* __restrict__ W_in,
                            const float* __restrict__ W_o1,
                            const float* __restrict__ W_root,
                            const float* __restrict__ W_rel,
                            __nv_bfloat16* __restrict__ Wt_des,
                            __nv_bfloat16* __restrict__ Wt_tweet,
                            __nv_bfloat16* __restrict__ Wt_prop,
                            __nv_bfloat16* __restrict__ Wt_in,
                            __nv_bfloat16* __restrict__ Wt_o1,
                            __nv_bfloat16* __restrict__ Wt_cat) {
    int idx = blockIdx.x * blockDim.x + threadIdx.x;
    if (idx < 24576) {
        tr_one(W_des, Wt_des, idx, 768, 32, 768);
    } else if ((idx -= 24576) < 24576) {
        tr_one(W_tweet, Wt_tweet, idx, 768, 32, 768);
    } else if ((idx -= 24576) < 2048) {
        tr_one(W_prop, Wt_prop, idx, 14, 32, 64);
    } else if ((idx -= 2048) < 16384) {
        tr_one(W_in, Wt_in, idx, 96, 128, 128);
    } else if ((idx -= 16384) < 16384) {
        tr_one(W_o1, Wt_o1, idx, 128, 128, 128);
    } else if ((idx -= 16384) < 49152) {
        int n = idx / 384, k = idx % 384;
        float v = (k < 128) ? W_root[k * 128 + n] : W_rel[(k - 128) * 128 + n];
        Wt_cat[idx] = __float2bfloat16_rn(v);
    }
}

// ------------------------- mma primitives ----------------------------------

#define LDMX4(r0, r1, r2, r3, addr)                                           \
    asm volatile("ldmatrix.sync.aligned.m8n8.x4.shared.b16 {%0,%1,%2,%3}, [%4];" \
                 : "=r"(r0), "=r"(r1), "=r"(r2), "=r"(r3) : "r"(addr))
#define LDMX2(r0, r1, addr)                                                   \
    asm volatile("ldmatrix.sync.aligned.m8n8.x2.shared.b16 {%0,%1}, [%2];"    \
                 : "=r"(r0), "=r"(r1) : "r"(addr))
#define MMA16816(c, a, b)                                                     \
    asm volatile(                                                             \
        "mma.sync.aligned.m16n8k16.row.col.f32.bf16.bf16.f32 "                \
        "{%0,%1,%2,%3}, {%4,%5,%6,%7}, {%8,%9}, {%0,%1,%2,%3};"               \
        : "+f"((c)[0]), "+f"((c)[1]), "+f"((c)[2]), "+f"((c)[3])              \
        : "r"((a)[0]), "r"((a)[1]), "r"((a)[2]), "r"((a)[3]),                 \
          "r"((b)[0]), "r"((b)[1]))

// ------------------------- fused encoder GEMM + edge count ------------------
// Blocks [0, ncnt): CSR count (grid-stride histogram).
// Blocks [ncnt, ncnt + 3*gm): encoder slices (des | tweet | prop).

__global__ void __launch_bounds__(128) gemm_enc3_count(
    const float* __restrict__ des, const float* __restrict__ tweet,
    const float* __restrict__ prop,
    const __nv_bfloat16* __restrict__ Wt_des,
    const __nv_bfloat16* __restrict__ Wt_tweet,
    const __nv_bfloat16* __restrict__ Wt_prop,
    const float* __restrict__ b_des, const float* __restrict__ b_tweet,
    const float* __restrict__ b_prop, __nv_bfloat16* __restrict__ Bout,
    int M, int gm,
    const int* __restrict__ dstE, const int* __restrict__ etE, int E,
    int* __restrict__ cnt, int ncnt) {
    if (blockIdx.x < (unsigned)ncnt) {
        for (int i = blockIdx.x * 128 + threadIdx.x; i < E; i += ncnt * 128)
            atomicAdd(&cnt[dstE[i] * 2 + etE[i]], 1);
        return;
    }
    const int flat = blockIdx.x - ncnt;
    const int bx = flat % gm, by = flat / gm;

    const float* A;
    const __nv_bfloat16* Wt;
    const float* bias;
    __nv_bfloat16* C;
    int lda, K, ldw;
    if (by == 0) {
        A = des; Wt = Wt_des; bias = b_des; C = Bout; lda = 768; K = 768; ldw = 768;
    } else if (by == 1) {
        A = tweet; Wt = Wt_tweet; bias = b_tweet; C = Bout + 32; lda = 768; K = 768; ldw = 768;
    } else {
        A = prop; Wt = Wt_prop; bias = b_prop; C = Bout + 64; lda = 14; K = 14; ldw = 64;
    }
    const int ldc = 384;

    constexpr int STR = 40;
    __shared__ __nv_bfloat16 sA[128 * STR];
    __shared__ __nv_bfloat16 sB[32 * STR];

    const int tid = threadIdx.x;
    const int wid = tid >> 5, lane = tid & 31;
    const int row0 = bx * 128;
    const uint32_t baseA = smem_u32(sA);
    const uint32_t baseB = smem_u32(sB);

    float acc[2][4][4];
#pragma unroll
    for (int i = 0; i < 2; i++)
#pragma unroll
        for (int j = 0; j < 4; j++)
#pragma unroll
            for (int q = 0; q < 4; q++) acc[i][j][q] = 0.f;

    uint32_t aAddr[2];
#pragma unroll
    for (int i = 0; i < 2; i++)
        aAddr[i] = baseA + (uint32_t)(((wid * 32 + i * 16 + (lane & 15)) * STR +
                                       ((lane >> 4) * 8)) * 2);
    uint32_t bAddr[4];
#pragma unroll
    for (int j = 0; j < 4; j++)
        bAddr[j] = baseB + (uint32_t)(((j * 8 + (lane & 7)) * STR +
                                       (((lane >> 3) & 1) * 8)) * 2);

    const int nchunks = (K + 31) >> 5;
    for (int c = 0; c < nchunks; c++) {
        const int k0 = c << 5;
#pragma unroll 2
        for (int idx = tid; idx < 128 * 4; idx += 128) {
            int r = idx >> 2, g = idx & 3;
            int gr = row0 + r, gc0 = k0 + g * 8;
            uint4 val;
            if (gr < M && gc0 + 7 < K && (lda & 3) == 0) {
                const float4* p = (const float4*)(A + (size_t)gr * lda + gc0);
                float4 v0 = p[0], v1 = p[1];
                __nv_bfloat162 h0 = __floats2bfloat162_rn(v0.x, v0.y);
                __nv_bfloat162 h1 = __floats2bfloat162_rn(v0.z, v0.w);
                __nv_bfloat162 h2 = __floats2bfloat162_rn(v1.x, v1.y);
                __nv_bfloat162 h3 = __floats2bfloat162_rn(v1.z, v1.w);
                val.x = *(uint32_t*)&h0; val.y = *(uint32_t*)&h1;
                val.z = *(uint32_t*)&h2; val.w = *(uint32_t*)&h3;
            } else {
                float v[8];
#pragma unroll
                for (int e = 0; e < 8; e++) {
                    int gc = gc0 + e;
                    v[e] = (gr < M && gc < K) ? A[(size_t)gr * lda + gc] : 0.f;
                }
                __nv_bfloat162 h0 = __floats2bfloat162_rn(v[0], v[1]);
                __nv_bfloat162 h1 = __floats2bfloat162_rn(v[2], v[3]);
                __nv_bfloat162 h2 = __floats2bfloat162_rn(v[4], v[5]);
                __nv_bfloat162 h3 = __floats2bfloat162_rn(v[6], v[7]);
                val.x = *(uint32_t*)&h0; val.y = *(uint32_t*)&h1;
                val.z = *(uint32_t*)&h2; val.w = *(uint32_t*)&h3;
            }
            *(uint4*)(sA + r * STR + g * 8) = val;
        }
        {
            int n = tid >> 2, g = tid & 3;
            uint4 val = *(const uint4*)(Wt + (size_t)n * ldw + k0 + g * 8);
            *(uint4*)(sB + n * STR + g * 8) = val;
        }
        __syncthreads();

#pragma unroll
        for (int s = 0; s < 2; s++) {
            uint32_t bfr[4][2];
#pragma unroll
            for (int j = 0; j < 4; j++)
                LDMX2(bfr[j][0], bfr[j][1], bAddr[j] + s * 32);
#pragma unroll
            for (int i = 0; i < 2; i++) {
                uint32_t afr[4];
                LDMX4(afr[0], afr[1], afr[2], afr[3], aAddr[i] + s * 32);
#pragma unroll
                for (int j = 0; j < 4; j++) MMA16816(acc[i][j], afr, bfr[j]);
            }
        }
        __syncthreads();
    }

    const int qrow = lane >> 2, qcol = (lane & 3) * 2;
#pragma unroll
    for (int i = 0; i < 2; i++) {
#pragma unroll
        for (int j = 0; j < 4; j++) {
            int gc = j * 8 + qcol;
            float b0 = bias[gc], b1 = bias[gc + 1];
            int gr0 = row0 + wid * 32 + i * 16 + qrow;
            float v0 = acc[i][j][0] + b0, v1 = acc[i][j][1] + b1;
            float v2 = acc[i][j][2] + b0, v3 = acc[i][j][3] + b1;
            v0 = (v0 >= 0.f) ? v0 : 0.01f * v0;
            v1 = (v1 >= 0.f) ? v1 : 0.01f * v1;
            v2 = (v2 >= 0.f) ? v2 : 0.01f * v2;
            v3 = (v3 >= 0.f) ? v3 : 0.01f * v3;
            if (gr0 < M) {
                __nv_bfloat162 h = __floats2bfloat162_rn(v0, v1);
                *(uint32_t*)(C + (size_t)gr0 * ldc + gc) = *(uint32_t*)&h;
            }
            if (gr0 + 8 < M) {
                __nv_bfloat162 h = __floats2bfloat162_rn(v2, v3);
                *(uint32_t*)(C + (size_t)(gr0 + 8) * ldc + gc) = *(uint32_t*)&h;
            }
        }
    }
}

// ------------------------- main GEMM (bf16 A, R10 exact) -------------------
// C[M,128](bf16, ldc) = act( A[M,K](bf16) @ Wt[128,K]^T + bias )
// BM=128, BN=128, BK=32; 8 warps (4x2), warp tile 32x64.
// HEAD: softmax(lrelu(acc+bias) @ W_o2 + b_o2) -> fp32 [M,2].
// PLACE: blocks [0, nplace) run CSR place instead (fused independent work).

template <bool HEAD, bool PLACE>
__global__ void __launch_bounds__(256) gemm_mma(
    const __nv_bfloat16* __restrict__ Aptr, int lda,
    const __nv_bfloat16* __restrict__ Wt, int ldw,
    const float* __restrict__ bias, __nv_bfloat16* __restrict__ C, int ldc,
    int M, int K, int act,
    const float* __restrict__ W_o2, const float* __restrict__ b_o2,
    float* __restrict__ outp,
    const int* __restrict__ srcE, const int* __restrict__ dstE,
    const int* __restrict__ etE, int E, const int* __restrict__ seg_start,
    int* __restrict__ cursor, int* __restrict__ perm, int nplace) {
    if (PLACE) {
        if (blockIdx.x < (unsigned)nplace) {
            for (int i = blockIdx.x * 256 + threadIdx.x; i < E;
                 i += nplace * 256) {
                int seg = dstE[i] * 2 + etE[i];
                int p = atomicAdd(&cursor[seg], 1);
                perm[seg_start[seg] + p] = srcE[i];
            }
            return;
        }
    }
    const int bx = PLACE ? (blockIdx.x - nplace) : blockIdx.x;

    constexpr int BN = 128;
    constexpr int THREADS = 256;
    constexpr int WN = 64;
    constexpr int NATOMS = 8;
    constexpr int STR = 40;

    __shared__ __nv_bfloat16 sA[128 * STR];
    __shared__ __nv_bfloat16 sB[BN * STR];

    const int tid = threadIdx.x;
    const int wid = tid >> 5, lane = tid & 31;
    const int wm = wid & 3, wn = wid >> 2;
    const int row0 = bx * 128;
    const uint32_t baseA = smem_u32(sA);
    const uint32_t baseB = smem_u32(sB);

    float acc[2][NATOMS][4];
#pragma unroll
    for (int i = 0; i < 2; i++)
#pragma unroll
        for (int j = 0; j < NATOMS; j++)
#pragma unroll
            for (int q = 0; q < 4; q++) acc[i][j][q] = 0.f;

    uint32_t aAddr[2];
#pragma unroll
    for (int i = 0; i < 2; i++)
        aAddr[i] = baseA + (uint32_t)(((wm * 32 + i * 16 + (lane & 15)) * STR +
                                       ((lane >> 4) * 8)) * 2);
    uint32_t bAddr[NATOMS];
#pragma unroll
    for (int j = 0; j < NATOMS; j++)
        bAddr[j] = baseB + (uint32_t)(((wn * WN + j * 8 + (lane & 7)) * STR +
                                       (((lane >> 3) & 1) * 8)) * 2);

    const int nchunks = (K + 31) >> 5;
    for (int c = 0; c < nchunks; c++) {
        const int k0 = c << 5;
#pragma unroll 2
        for (int idx = tid; idx < 128 * 4; idx += THREADS) {
            int r = idx >> 2, g = idx & 3;
            int gr = row0 + r;
            uint4 val = (gr < M)
                            ? *(const uint4*)(Aptr + (size_t)gr * lda + k0 + g * 8)
                            : make_uint4(0, 0, 0, 0);
            *(uint4*)(sA + r * STR + g * 8) = val;
        }
#pragma unroll 2
        for (int idx = tid; idx < BN * 4; idx += THREADS) {
            int n = idx >> 2, g = idx & 3;
            uint4 val = *(const uint4*)(Wt + (size_t)n * ldw + k0 + g * 8);
            *(uint4*)(sB + n * STR + g * 8) = val;
        }
        __syncthreads();

        // L2 prefetch of next chunk's A rows
        if (c + 1 < nchunks) {
            int r = tid >> 1;
            if ((tid & 1) == 0) {
                int gr = row0 + r;
                if (gr < M) {
                    const void* p = (const void*)(Aptr + (size_t)gr * lda +
                                                  ((c + 1) << 5));
                    asm volatile("prefetch.global.L2 [%0];" :: "l"(p));
                }
            }
        }

#pragma unroll
        for (int s = 0; s < 2; s++) {
            uint32_t bfr[NATOMS][2];
#pragma unroll
            for (int j = 0; j < NATOMS; j++)
                LDMX2(bfr[j][0], bfr[j][1], bAddr[j] + s * 32);
#pragma unroll
            for (int i = 0; i < 2; i++) {
                uint32_t afr[4];
                LDMX4(afr[0], afr[1], afr[2], afr[3], aAddr[i] + s * 32);
#pragma unroll
                for (int j = 0; j < NATOMS; j++) MMA16816(acc[i][j], afr, bfr[j]);
            }
        }
        __syncthreads();
    }

    const int qrow = lane >> 2, qcol = (lane & 3) * 2;

    if (!HEAD) {
#pragma unroll
        for (int i = 0; i < 2; i++) {
#pragma unroll
            for (int j = 0; j < NATOMS; j++) {
                int gc = wn * WN + j * 8 + qcol;
                float b0 = bias[gc], b1 = bias[gc + 1];
                int gr0 = row0 + wm * 32 + i * 16 + qrow;
                float v0 = acc[i][j][0] + b0, v1 = acc[i][j][1] + b1;
                float v2 = acc[i][j][2] + b0, v3 = acc[i][j][3] + b1;
                if (act) {
                    v0 = (v0 >= 0.f) ? v0 : 0.01f * v0;
                    v1 = (v1 >= 0.f) ? v1 : 0.01f * v1;
                    v2 = (v2 >= 0.f) ? v2 : 0.01f * v2;
                    v3 = (v3 >= 0.f) ? v3 : 0.01f * v3;
                }
                if (gr0 < M) {
                    __nv_bfloat162 h = __floats2bfloat162_rn(v0, v1);
                    *(uint32_t*)(C + (size_t)gr0 * ldc + gc) = *(uint32_t*)&h;
                }
                if (gr0 + 8 < M) {
                    __nv_bfloat162 h = __floats2bfloat162_rn(v2, v3);
                    *(uint32_t*)(C + (size_t)(gr0 + 8) * ldc + gc) = *(uint32_t*)&h;
                }
            }
        }
    } else {
        __shared__ float sred[2][128][2];
        float p0[4] = {0.f, 0.f, 0.f, 0.f};
        float p1[4] = {0.f, 0.f, 0.f, 0.f};
#pragma unroll
        for (int i = 0; i < 2; i++) {
#pragma unroll
            for (int j = 0; j < NATOMS; j++) {
                int gc = wn * WN + j * 8 + qcol;
                float b0 = bias[gc], b1 = bias[gc + 1];
                float v0 = acc[i][j][0] + b0, v1 = acc[i][j][1] + b1;
                float v2 = acc[i][j][2] + b0, v3 = acc[i][j][3] + b1;
                v0 = (v0 >= 0.f) ? v0 : 0.01f * v0;
                v1 = (v1 >= 0.f) ? v1 : 0.01f * v1;
                v2 = (v2 >= 0.f) ? v2 : 0.01f * v2;
                v3 = (v3 >= 0.f) ? v3 : 0.01f * v3;
                float w00 = W_o2[gc * 2], w01 = W_o2[gc * 2 + 1];
                float w10 = W_o2[(gc + 1) * 2], w11 = W_o2[(gc + 1) * 2 + 1];
                p0[i * 2 + 0] += v0 * w00 + v1 * w10;
                p1[i * 2 + 0] += v0 * w01 + v1 * w11;
                p0[i * 2 + 1] += v2 * w00 + v3 * w10;
                p1[i * 2 + 1] += v2 * w01 + v3 * w11;
            }
        }
#pragma unroll
        for (int off = 1; off <= 2; off <<= 1) {
#pragma unroll
            for (int k = 0; k < 4; k++) {
                p0[k] += __shfl_xor_sync(0xFFFFFFFFu, p0[k], off);
                p1[k] += __shfl_xor_sync(0xFFFFFFFFu, p1[k], off);
            }
        }
        if ((lane & 3) == 0) {
#pragma unroll
            for (int k = 0; k < 4; k++) {
                int row = wm * 32 + (k >> 1) * 16 + qrow + (k & 1) * 8;
                sred[wn][row][0] = p0[k];
                sred[wn][row][1] = p1[k];
            }
        }
        __syncthreads();
        if (tid < 128) {
            int gr = row0 + tid;
            if (gr < M) {
                float l0 = b_o2[0] + sred[0][tid][0] + sred[1][tid][0];
                float l1 = b_o2[1] + sred[0][tid][1] + sred[1][tid][1];
                float m = fmaxf(l0, l1);
                float e0 = __expf(l0 - m), e1 = __expf(l1 - m);
                float inv = 1.f / (e0 + e1);
                outp[(size_t)gr * 2] = e0 * inv;
                outp[(size_t)gr * 2 + 1] = e1 * inv;
            }
        }
    }
}

// ------------------------- Aggregation (uint4, 2 edges/warp/iter) ----------
// Lanes 0-15 cover all 128 cols (8 cols/lane) of edge e; lanes 16-31 of
// edge e+1. Unroll x2 -> 4 edges in flight. Halves combined via shfl.

__global__ void aggregate_kernel(__nv_bfloat16* __restrict__ buf,
                                 const int* __restrict__ seg_start,
                                 const int* __restrict__ cnt,
                                 const int* __restrict__ perm, int NR) {
    int w = blockIdx.x * (blockDim.x >> 5) + (threadIdx.x >> 5);
    if (w >= NR) return;
    int lane = threadIdx.x & 31;
    int half = lane >> 4;       // 0 or 1: which edge of the pair
    int hl = lane & 15;         // column group: cols hl*8 .. hl*8+7
    int start = seg_start[w];
    int deg = cnt[w];
    int end = start + deg;
    float a[8];
#pragma unroll
    for (int k = 0; k < 8; k++) a[k] = 0.f;

#define ACC8(v)                                                               \
    {                                                                         \
        float2 f0 = __bfloat1622float2(*(__nv_bfloat162*)&(v).x);             \
        float2 f1 = __bfloat1622float2(*(__nv_bfloat162*)&(v).y);             \
        float2 f2 = __bfloat1622float2(*(__nv_bfloat162*)&(v).z);             \
        float2 f3 = __bfloat1622float2(*(__nv_bfloat162*)&(v).w);             \
        a[0] += f0.x; a[1] += f0.y; a[2] += f1.x; a[3] += f1.y;               \
        a[4] += f2.x; a[5] += f2.y; a[6] += f3.x; a[7] += f3.y;               \
    }

    int e = start;
    for (; e + 3 < end; e += 4) {
        int s0 = perm[e + half];
        int s1 = perm[e + 2 + half];
        uint4 v0 = *(const uint4*)(buf + (size_t)s0 * 384 + hl * 8);
        uint4 v1 = *(const uint4*)(buf + (size_t)s1 * 384 + hl * 8);
        ACC8(v0) ACC8(v1)
    }
    for (; e + 1 < end; e += 2) {
        int s = perm[e + half];
        uint4 v = *(const uint4*)(buf + (size_t)s * 384 + hl * 8);
        ACC8(v)
    }
    if (e < end && half == 0) {
        int s = perm[e];
        uint4 v = *(const uint4*)(buf + (size_t)s * 384 + hl * 8);
        ACC8(v)
    }
#undef ACC8

    // combine the two halves (lane i += lane i^16)
#pragma unroll
    for (int k = 0; k < 8; k++)
        a[k] += __shfl_xor_sync(0xFFFFFFFFu, a[k], 16);

    if (half == 0) {
        float inv = 1.f / (float)max(deg, 1);
        __nv_bfloat162 h0 = __floats2bfloat162_rn(a[0] * inv, a[1] * inv);
        __nv_bfloat162 h1 = __floats2bfloat162_rn(a[2] * inv, a[3] * inv);
        __nv_bfloat162 h2 = __floats2bfloat162_rn(a[4] * inv, a[5] * inv);
        __nv_bfloat162 h3 = __floats2bfloat162_rn(a[6] * inv, a[7] * inv);
        uint4 outv;
        outv.x = *(uint32_t*)&h0; outv.y = *(uint32_t*)&h1;
        outv.z = *(uint32_t*)&h2; outv.w = *(uint32_t*)&h3;
        int node = w >> 1, r = w & 1;
        *(uint4*)(buf + (size_t)node * 384 + 128 + r * 128 + hl * 8) = outv;
    }
}

// ------------------------- Launch ------------------------------------------

extern "C" void kernel_launch(void* const* d_in, const int* in_sizes, int n_in,
                              void* d_out, int out_size) {
    const float* des     = (const float*)d_in[0];
    const float* tweet   = (const float*)d_in[1];
    const float* prop    = (const float*)d_in[2];
    const int*   eidx    = (const int*)d_in[3];
    const int*   etype   = (const int*)d_in[4];
    const float* W_des   = (const float*)d_in[5];
    const float* b_des   = (const float*)d_in[6];
    const float* W_tweet = (const float*)d_in[7];
    const float* b_tweet = (const float*)d_in[8];
    const float* W_prop  = (const float*)d_in[9];
    const float* b_prop  = (const float*)d_in[10];
    const float* W_in    = (const float*)d_in[11];
    const float* b_in    = (const float*)d_in[12];
    const float* W_rel   = (const float*)d_in[13];
    const float* W_root  = (const float*)d_in[14];
    const float* b_rgcn  = (const float*)d_in[15];
    const float* W_o1    = (const float*)d_in[16];
    const float* b_o1    = (const float*)d_in[17];
    const float* W_o2    = (const float*)d_in[18];
    const float* b_o2    = (const float*)d_in[19];

    const int N = in_sizes[0] / 768;
    const int E = in_sizes[4];
    const int NR = N * 2;
    const int* src = eidx;
    const int* dst = eidx + E;

    __nv_bfloat16 *A, *B, *Wt_des, *Wt_tweet, *Wt_prop, *Wt_in, *Wt_cat, *Wt_o1;
    cudaGetSymbolAddress((void**)&A, g_A);
    cudaGetSymbolAddress((void**)&B, g_B);
    cudaGetSymbolAddress((void**)&Wt_des, g_Wt_des);
    cudaGetSymbolAddress((void**)&Wt_tweet, g_Wt_tweet);
    cudaGetSymbolAddress((void**)&Wt_prop, g_Wt_prop);
    cudaGetSymbolAddress((void**)&Wt_in, g_Wt_in);
    cudaGetSymbolAddress((void**)&Wt_cat, g_Wt_cat);
    cudaGetSymbolAddress((void**)&Wt_o1, g_Wt_o1);
    int *perm, *seg_start, *cntcur;
    cudaGetSymbolAddress((void**)&perm, g_perm);
    cudaGetSymbolAddress((void**)&seg_start, g_seg_start);
    cudaGetSymbolAddress((void**)&cntcur, g_cntcur);
    int* cnt = cntcur;
    int* cursor = cntcur + NRSEG;
    int* total = cntcur + 2 * NRSEG;

    const int gm = (N + 127) / 128;
    const int ncnt = 2048;
    const int nplace = 1024;

    // launch 1: zero cnt + cursor + total in one memset
    cudaMemsetAsync(cntcur, 0, (size_t)(2 * NRSEG + 1) * sizeof(int));
    // launch 2: weight prep
    prep_kernel<<<(PREP_TOTAL + 255) / 256, 256>>>(
        W_des, W_tweet, W_prop, W_in, W_o1, W_root, W_rel, Wt_des, Wt_tweet,
        Wt_prop, Wt_in, Wt_o1, Wt_cat);
    // launch 3: encoders + CSR count
    gemm_enc3_count<<<ncnt + gm * 3, 128>>>(des, tweet, prop, Wt_des, Wt_tweet,
                                            Wt_prop, b_des, b_tweet, b_prop, B,
                                            N, gm, dst, etype, E, cnt, ncnt);
    // launch 4: segment offsets (unordered CSR)
    seg_offsets_kernel<<<(NR + 1023) / 1024, 1024>>>(cnt, seg_start, total, NR);
    // launch 5: cat96 @ W_in -> A cols 0..127, fused with CSR place
    gemm_mma<false, true><<<nplace + gm, 256>>>(
        B, 384, Wt_in, 128, b_in, A, 384, N, 96, 1, nullptr, nullptr, nullptr,
        src, dst, etype, E, seg_start, cursor, perm, nplace);
    // launch 6 (ncu sample): aggregate layer 1
    aggregate_kernel<<<(NR + 7) / 8, 256>>>(A, seg_start, cnt, perm, NR);
    // launch 7: rgcn layer 1 GEMM
    gemm_mma<false, false><<<gm, 256>>>(A, 384, Wt_cat, 384, b_rgcn, B, 384, N,
                                        384, 0, nullptr, nullptr, nullptr,
                                        nullptr, nullptr, nullptr, 0, nullptr,
                                        nullptr, nullptr, 0);
    // launch 8: aggregate layer 2
    aggregate_kernel<<<(NR + 7) / 8, 256>>>(B, seg_start, cnt, perm, NR);
    // launch 9: rgcn layer 2 GEMM
    gemm_mma<false, false><<<gm, 256>>>(B, 384, Wt_cat, 384, b_rgcn, A, 384, N,
                                        384, 0, nullptr, nullptr, nullptr,
                                        nullptr, nullptr, nullptr, 0, nullptr,
                                        nullptr, nullptr, 0);
    // launch 10: head
    gemm_mma<true, false><<<gm, 256>>>(A, 384, Wt_o1, 128, b_o1, nullptr, 384,
                                       N, 128, 1, W_o2, b_o2, (float*)d_out,
                                       nullptr, nullptr, nullptr, 0, nullptr,
                                       nullptr, nullptr, 0);
}

// round 15
// speedup vs baseline: 1.5073x; 1.0452x over previous
#include <cuda_runtime.h>
#include <cuda_bf16.h>
#include <cstdint>

// ---------------------------------------------------------------------------
// BotRGCN on GB300 — bf16 mma.sync (m16n8k16) pipeline.
//   rgcn(x) = [x | mean_0(x) | mean_1(x)] @ [W_root; W_rel0; W_rel1] + b
// R14: exact R10 restore (best 539.8us) + ONE isolated change: gemm_mma
// mainloop is cp.async double-buffered (the only untested fix for its
// measured issue=10%/occ=24% latency-bound signature).
// ---------------------------------------------------------------------------

#define MAXN 100000
#define MAXE 3200000
#define NRSEG (MAXN * 2)

__device__ __align__(256) __nv_bfloat16 g_A[(size_t)MAXN * 384];
__device__ __align__(256) __nv_bfloat16 g_B[(size_t)MAXN * 384];
__device__ __align__(256) __nv_bfloat16 g_Wt_des[32 * 768];
__device__ __align__(256) __nv_bfloat16 g_Wt_tweet[32 * 768];
__device__ __align__(256) __nv_bfloat16 g_Wt_prop[32 * 64];
__device__ __align__(256) __nv_bfloat16 g_Wt_in[128 * 128];
__device__ __align__(256) __nv_bfloat16 g_Wt_cat[128 * 384];
__device__ __align__(256) __nv_bfloat16 g_Wt_o1[128 * 128];
__device__ __align__(256) int g_perm[MAXE];
__device__ __align__(256) int g_seg_start[NRSEG];
// cnt | cursor | total : one contiguous region, zeroed by a single memset
__device__ __align__(256) int g_cntcur[2 * NRSEG + 1];

__device__ __forceinline__ uint32_t smem_u32(const void* p) {
    uint32_t a;
    asm("{ .reg .u64 t; cvta.to.shared.u64 t, %1; cvt.u32.u64 %0, t; }"
        : "=r"(a) : "l"(p));
    return a;
}

#define CP_ASYNC16(dst, src, srcbytes)                                        \
    asm volatile("cp.async.cg.shared.global [%0], [%1], 16, %2;"              \
                 :: "r"(dst), "l"(src), "r"(srcbytes))
#define CP_COMMIT() asm volatile("cp.async.commit_group;" ::: "memory")
#define CP_WAIT(n) asm volatile("cp.async.wait_group %0;" :: "n"(n) : "memory")

// ------------------------- segment offsets (unordered CSR) -----------------

__global__ void seg_offsets_kernel(const int* __restrict__ cnt,
                                   int* __restrict__ seg_start,
                                   int* __restrict__ total, int n) {
    __shared__ int s[1024];
    __shared__ int base;
    int idx = blockIdx.x * 1024 + threadIdx.x;
    int v = (idx < n) ? cnt[idx] : 0;
    s[threadIdx.x] = v;
    __syncthreads();
    for (int off = 1; off < 1024; off <<= 1) {
        int t = (threadIdx.x >= off) ? s[threadIdx.x - off] : 0;
        __syncthreads();
        s[threadIdx.x] += t;
        __syncthreads();
    }
    if (threadIdx.x == 1023) base = atomicAdd(total, s[1023]);
    __syncthreads();
    if (idx < n) seg_start[idx] = base + s[threadIdx.x] - v;
}

// ------------------------- Weight prep (single launch) ---------------------

__device__ __forceinline__ void tr_one(const float* in, __nv_bfloat16* out,
                                       int idx, int K, int Nw, int Kpad) {
    int n = idx / Kpad, k = idx % Kpad;
    out[idx] = (k < K) ? __float2bfloat16_rn(in[k * Nw + n])
                       : __float2bfloat16_rn(0.f);
}

#define PREP_TOTAL (24576 + 24576 + 2048 + 16384 + 16384 + 49152)

__global__ void prep_kernel(const float* __restrict__ W_des,
                            const float* __restrict__ W_tweet,
                            const float* __restrict__ W_prop,
                            const float* __restrict__ W_in,
                            const float* __restrict__ W_o1,
                            const float* __restrict__ W_root,
                            const float* __restrict__ W_rel,
                            __nv_bfloat16* __restrict__ Wt_des,
                            __nv_bfloat16* __restrict__ Wt_tweet,
                            __nv_bfloat16* __restrict__ Wt_prop,
                            __nv_bfloat16* __restrict__ Wt_in,
                            __nv_bfloat16* __restrict__ Wt_o1,
                            __nv_bfloat16* __restrict__ Wt_cat) {
    int idx = blockIdx.x * blockDim.x + threadIdx.x;
    if (idx < 24576) {
        tr_one(W_des, Wt_des, idx, 768, 32, 768);
    } else if ((idx -= 24576) < 24576) {
        tr_one(W_tweet, Wt_tweet, idx, 768, 32, 768);
    } else if ((idx -= 24576) < 2048) {
        tr_one(W_prop, Wt_prop, idx, 14, 32, 64);
    } else if ((idx -= 2048) < 16384) {
        tr_one(W_in, Wt_in, idx, 96, 128, 128);
    } else if ((idx -= 16384) < 16384) {
        tr_one(W_o1, Wt_o1, idx, 128, 128, 128);
    } else if ((idx -= 16384) < 49152) {
        int n = idx / 384, k = idx % 384;
        float v = (k < 128) ? W_root[k * 128 + n] : W_rel[(k - 128) * 128 + n];
        Wt_cat[idx] = __float2bfloat16_rn(v);
    }
}

// ------------------------- mma primitives ----------------------------------

#define LDMX4(r0, r1, r2, r3, addr)                                           \
    asm volatile("ldmatrix.sync.aligned.m8n8.x4.shared.b16 {%0,%1,%2,%3}, [%4];" \
                 : "=r"(r0), "=r"(r1), "=r"(r2), "=r"(r3) : "r"(addr))
#define LDMX2(r0, r1, addr)                                                   \
    asm volatile("ldmatrix.sync.aligned.m8n8.x2.shared.b16 {%0,%1}, [%2];"    \
                 : "=r"(r0), "=r"(r1) : "r"(addr))
#define MMA16816(c, a, b)                                                     \
    asm volatile(                                                             \
        "mma.sync.aligned.m16n8k16.row.col.f32.bf16.bf16.f32 "                \
        "{%0,%1,%2,%3}, {%4,%5,%6,%7}, {%8,%9}, {%0,%1,%2,%3};"               \
        : "+f"((c)[0]), "+f"((c)[1]), "+f"((c)[2]), "+f"((c)[3])              \
        : "r"((a)[0]), "r"((a)[1]), "r"((a)[2]), "r"((a)[3]),                 \
          "r"((b)[0]), "r"((b)[1]))

// ------------------------- fused encoder GEMM + edge count ------------------
// Blocks [0, ncnt): CSR count (grid-stride histogram).
// Blocks [ncnt, ncnt + 3*gm): encoder slices (des | tweet | prop).

__global__ void __launch_bounds__(128) gemm_enc3_count(
    const float* __restrict__ des, const float* __restrict__ tweet,
    const float* __restrict__ prop,
    const __nv_bfloat16* __restrict__ Wt_des,
    const __nv_bfloat16* __restrict__ Wt_tweet,
    const __nv_bfloat16* __restrict__ Wt_prop,
    const float* __restrict__ b_des, const float* __restrict__ b_tweet,
    const float* __restrict__ b_prop, __nv_bfloat16* __restrict__ Bout,
    int M, int gm,
    const int* __restrict__ dstE, const int* __restrict__ etE, int E,
    int* __restrict__ cnt, int ncnt) {
    if (blockIdx.x < (unsigned)ncnt) {
        for (int i = blockIdx.x * 128 + threadIdx.x; i < E; i += ncnt * 128)
            atomicAdd(&cnt[dstE[i] * 2 + etE[i]], 1);
        return;
    }
    const int flat = blockIdx.x - ncnt;
    const int bx = flat % gm, by = flat / gm;

    const float* A;
    const __nv_bfloat16* Wt;
    const float* bias;
    __nv_bfloat16* C;
    int lda, K, ldw;
    if (by == 0) {
        A = des; Wt = Wt_des; bias = b_des; C = Bout; lda = 768; K = 768; ldw = 768;
    } else if (by == 1) {
        A = tweet; Wt = Wt_tweet; bias = b_tweet; C = Bout + 32; lda = 768; K = 768; ldw = 768;
    } else {
        A = prop; Wt = Wt_prop; bias = b_prop; C = Bout + 64; lda = 14; K = 14; ldw = 64;
    }
    const int ldc = 384;

    constexpr int STR = 40;
    __shared__ __nv_bfloat16 sA[128 * STR];
    __shared__ __nv_bfloat16 sB[32 * STR];

    const int tid = threadIdx.x;
    const int wid = tid >> 5, lane = tid & 31;
    const int row0 = bx * 128;
    const uint32_t baseA = smem_u32(sA);
    const uint32_t baseB = smem_u32(sB);

    float acc[2][4][4];
#pragma unroll
    for (int i = 0; i < 2; i++)
#pragma unroll
        for (int j = 0; j < 4; j++)
#pragma unroll
            for (int q = 0; q < 4; q++) acc[i][j][q] = 0.f;

    uint32_t aAddr[2];
#pragma unroll
    for (int i = 0; i < 2; i++)
        aAddr[i] = baseA + (uint32_t)(((wid * 32 + i * 16 + (lane & 15)) * STR +
                                       ((lane >> 4) * 8)) * 2);
    uint32_t bAddr[4];
#pragma unroll
    for (int j = 0; j < 4; j++)
        bAddr[j] = baseB + (uint32_t)(((j * 8 + (lane & 7)) * STR +
                                       (((lane >> 3) & 1) * 8)) * 2);

    const int nchunks = (K + 31) >> 5;
    for (int c = 0; c < nchunks; c++) {
        const int k0 = c << 5;
#pragma unroll 2
        for (int idx = tid; idx < 128 * 4; idx += 128) {
            int r = idx >> 2, g = idx & 3;
            int gr = row0 + r, gc0 = k0 + g * 8;
            uint4 val;
            if (gr < M && gc0 + 7 < K && (lda & 3) == 0) {
                const float4* p = (const float4*)(A + (size_t)gr * lda + gc0);
                float4 v0 = p[0], v1 = p[1];
                __nv_bfloat162 h0 = __floats2bfloat162_rn(v0.x, v0.y);
                __nv_bfloat162 h1 = __floats2bfloat162_rn(v0.z, v0.w);
                __nv_bfloat162 h2 = __floats2bfloat162_rn(v1.x, v1.y);
                __nv_bfloat162 h3 = __floats2bfloat162_rn(v1.z, v1.w);
                val.x = *(uint32_t*)&h0; val.y = *(uint32_t*)&h1;
                val.z = *(uint32_t*)&h2; val.w = *(uint32_t*)&h3;
            } else {
                float v[8];
#pragma unroll
                for (int e = 0; e < 8; e++) {
                    int gc = gc0 + e;
                    v[e] = (gr < M && gc < K) ? A[(size_t)gr * lda + gc] : 0.f;
                }
                __nv_bfloat162 h0 = __floats2bfloat162_rn(v[0], v[1]);
                __nv_bfloat162 h1 = __floats2bfloat162_rn(v[2], v[3]);
                __nv_bfloat162 h2 = __floats2bfloat162_rn(v[4], v[5]);
                __nv_bfloat162 h3 = __floats2bfloat162_rn(v[6], v[7]);
                val.x = *(uint32_t*)&h0; val.y = *(uint32_t*)&h1;
                val.z = *(uint32_t*)&h2; val.w = *(uint32_t*)&h3;
            }
            *(uint4*)(sA + r * STR + g * 8) = val;
        }
        {
            int n = tid >> 2, g = tid & 3;
            uint4 val = *(const uint4*)(Wt + (size_t)n * ldw + k0 + g * 8);
            *(uint4*)(sB + n * STR + g * 8) = val;
        }
        __syncthreads();

#pragma unroll
        for (int s = 0; s < 2; s++) {
            uint32_t bfr[4][2];
#pragma unroll
            for (int j = 0; j < 4; j++)
                LDMX2(bfr[j][0], bfr[j][1], bAddr[j] + s * 32);
#pragma unroll
            for (int i = 0; i < 2; i++) {
                uint32_t afr[4];
                LDMX4(afr[0], afr[1], afr[2], afr[3], aAddr[i] + s * 32);
#pragma unroll
                for (int j = 0; j < 4; j++) MMA16816(acc[i][j], afr, bfr[j]);
            }
        }
        __syncthreads();
    }

    const int qrow = lane >> 2, qcol = (lane & 3) * 2;
#pragma unroll
    for (int i = 0; i < 2; i++) {
#pragma unroll
        for (int j = 0; j < 4; j++) {
            int gc = j * 8 + qcol;
            float b0 = bias[gc], b1 = bias[gc + 1];
            int gr0 = row0 + wid * 32 + i * 16 + qrow;
            float v0 = acc[i][j][0] + b0, v1 = acc[i][j][1] + b1;
            float v2 = acc[i][j][2] + b0, v3 = acc[i][j][3] + b1;
            v0 = (v0 >= 0.f) ? v0 : 0.01f * v0;
            v1 = (v1 >= 0.f) ? v1 : 0.01f * v1;
            v2 = (v2 >= 0.f) ? v2 : 0.01f * v2;
            v3 = (v3 >= 0.f) ? v3 : 0.01f * v3;
            if (gr0 < M) {
                __nv_bfloat162 h = __floats2bfloat162_rn(v0, v1);
                *(uint32_t*)(C + (size_t)gr0 * ldc + gc) = *(uint32_t*)&h;
            }
            if (gr0 + 8 < M) {
                __nv_bfloat162 h = __floats2bfloat162_rn(v2, v3);
                *(uint32_t*)(C + (size_t)(gr0 + 8) * ldc + gc) = *(uint32_t*)&h;
            }
        }
    }
}

// ------------------------- main GEMM (bf16 A, cp.async 2-stage) ------------
// C[M,128](bf16, ldc) = act( A[M,K](bf16) @ Wt[128,K]^T + bias )
// BM=128, BN=128, BK=32; 8 warps (4x2), warp tile 32x64; double-buffered
// smem via cp.async so the next chunk's loads overlap the current compute.
// HEAD: softmax(lrelu(acc+bias) @ W_o2 + b_o2) -> fp32 [M,2].
// PLACE: blocks [0, nplace) run CSR place instead (fused independent work).

template <bool HEAD, bool PLACE>
__global__ void __launch_bounds__(256) gemm_mma(
    const __nv_bfloat16* __restrict__ Aptr, int lda,
    const __nv_bfloat16* __restrict__ Wt, int ldw,
    const float* __restrict__ bias, __nv_bfloat16* __restrict__ C, int ldc,
    int M, int K, int act,
    const float* __restrict__ W_o2, const float* __restrict__ b_o2,
    float* __restrict__ outp,
    const int* __restrict__ srcE, const int* __restrict__ dstE,
    const int* __restrict__ etE, int E, const int* __restrict__ seg_start,
    int* __restrict__ cursor, int* __restrict__ perm, int nplace) {
    if (PLACE) {
        if (blockIdx.x < (unsigned)nplace) {
            for (int i = blockIdx.x * 256 + threadIdx.x; i < E;
                 i += nplace * 256) {
                int seg = dstE[i] * 2 + etE[i];
                int p = atomicAdd(&cursor[seg], 1);
                perm[seg_start[seg] + p] = srcE[i];
            }
            return;
        }
    }
    const int bx = PLACE ? (blockIdx.x - nplace) : blockIdx.x;

    constexpr int BN = 128;
    constexpr int THREADS = 256;
    constexpr int WN = 64;
    constexpr int NATOMS = 8;
    constexpr int STR = 40;
    constexpr uint32_t ABUF = 128 * STR * 2;  // bytes per buffer (A and B equal)

    __shared__ __nv_bfloat16 smem[(2 * 128 + 2 * BN) * STR];

    const int tid = threadIdx.x;
    const int wid = tid >> 5, lane = tid & 31;
    const int wm = wid & 3, wn = wid >> 2;
    const int row0 = bx * 128;
    const uint32_t base = smem_u32(smem);
    const uint32_t baseA = base;              // A0, A1
    const uint32_t baseB = base + 2 * ABUF;   // B0, B1

    float acc[2][NATOMS][4];
#pragma unroll
    for (int i = 0; i < 2; i++)
#pragma unroll
        for (int j = 0; j < NATOMS; j++)
#pragma unroll
            for (int q = 0; q < 4; q++) acc[i][j][q] = 0.f;

    uint32_t aAddr[2];
#pragma unroll
    for (int i = 0; i < 2; i++)
        aAddr[i] = baseA + (uint32_t)(((wm * 32 + i * 16 + (lane & 15)) * STR +
                                       ((lane >> 4) * 8)) * 2);
    uint32_t bAddr[NATOMS];
#pragma unroll
    for (int j = 0; j < NATOMS; j++)
        bAddr[j] = baseB + (uint32_t)(((wn * WN + j * 8 + (lane & 7)) * STR +
                                       (((lane >> 3) & 1) * 8)) * 2);

    const int nchunks = (K + 31) >> 5;

    auto issue = [&](int c) {
        const int k0 = c << 5;
        const uint32_t dA = baseA + (uint32_t)(c & 1) * ABUF;
        const uint32_t dB = baseB + (uint32_t)(c & 1) * ABUF;
#pragma unroll
        for (int it = 0; it < 2; it++) {
            int idx = tid + it * THREADS;   // 0..511
            int r = idx >> 2, g = idx & 3;
            int gr = row0 + r;
            int ok = (gr < M) ? 16 : 0;
            const __nv_bfloat16* src =
                Aptr + (size_t)(ok ? gr : 0) * lda + k0 + g * 8;
            CP_ASYNC16(dA + (uint32_t)((r * STR + g * 8) * 2), src, ok);
        }
#pragma unroll
        for (int it = 0; it < 2; it++) {
            int idx = tid + it * THREADS;
            int r = idx >> 2, g = idx & 3;
            const __nv_bfloat16* src = Wt + (size_t)r * ldw + k0 + g * 8;
            CP_ASYNC16(dB + (uint32_t)((r * STR + g * 8) * 2), src, 16);
        }
        CP_COMMIT();
    };

    issue(0);
    for (int c = 0; c < nchunks; c++) {
        if (c + 1 < nchunks) {
            issue(c + 1);
            CP_WAIT(1);
        } else {
            CP_WAIT(0);
        }
        __syncthreads();

        const uint32_t boff = (uint32_t)(c & 1) * ABUF;
#pragma unroll
        for (int s = 0; s < 2; s++) {
            uint32_t bfr[NATOMS][2];
#pragma unroll
            for (int j = 0; j < NATOMS; j++)
                LDMX2(bfr[j][0], bfr[j][1], bAddr[j] + boff + s * 32);
#pragma unroll
            for (int i = 0; i < 2; i++) {
                uint32_t afr[4];
                LDMX4(afr[0], afr[1], afr[2], afr[3], aAddr[i] + boff + s * 32);
#pragma unroll
                for (int j = 0; j < NATOMS; j++) MMA16816(acc[i][j], afr, bfr[j]);
            }
        }
        __syncthreads();
    }

    const int qrow = lane >> 2, qcol = (lane & 3) * 2;

    if (!HEAD) {
#pragma unroll
        for (int i = 0; i < 2; i++) {
#pragma unroll
            for (int j = 0; j < NATOMS; j++) {
                int gc = wn * WN + j * 8 + qcol;
                float b0 = bias[gc], b1 = bias[gc + 1];
                int gr0 = row0 + wm * 32 + i * 16 + qrow;
                float v0 = acc[i][j][0] + b0, v1 = acc[i][j][1] + b1;
                float v2 = acc[i][j][2] + b0, v3 = acc[i][j][3] + b1;
                if (act) {
                    v0 = (v0 >= 0.f) ? v0 : 0.01f * v0;
                    v1 = (v1 >= 0.f) ? v1 : 0.01f * v1;
                    v2 = (v2 >= 0.f) ? v2 : 0.01f * v2;
                    v3 = (v3 >= 0.f) ? v3 : 0.01f * v3;
                }
                if (gr0 < M) {
                    __nv_bfloat162 h = __floats2bfloat162_rn(v0, v1);
                    *(uint32_t*)(C + (size_t)gr0 * ldc + gc) = *(uint32_t*)&h;
                }
                if (gr0 + 8 < M) {
                    __nv_bfloat162 h = __floats2bfloat162_rn(v2, v3);
                    *(uint32_t*)(C + (size_t)(gr0 + 8) * ldc + gc) = *(uint32_t*)&h;
                }
            }
        }
    } else {
        __shared__ float sred[2][128][2];
        float p0[4] = {0.f, 0.f, 0.f, 0.f};
        float p1[4] = {0.f, 0.f, 0.f, 0.f};
#pragma unroll
        for (int i = 0; i < 2; i++) {
#pragma unroll
            for (int j = 0; j < NATOMS; j++) {
                int gc = wn * WN + j * 8 + qcol;
                float b0 = bias[gc], b1 = bias[gc + 1];
                float v0 = acc[i][j][0] + b0, v1 = acc[i][j][1] + b1;
                float v2 = acc[i][j][2] + b0, v3 = acc[i][j][3] + b1;
                v0 = (v0 >= 0.f) ? v0 : 0.01f * v0;
                v1 = (v1 >= 0.f) ? v1 : 0.01f * v1;
                v2 = (v2 >= 0.f) ? v2 : 0.01f * v2;
                v3 = (v3 >= 0.f) ? v3 : 0.01f * v3;
                float w00 = W_o2[gc * 2], w01 = W_o2[gc * 2 + 1];
                float w10 = W_o2[(gc + 1) * 2], w11 = W_o2[(gc + 1) * 2 + 1];
                p0[i * 2 + 0] += v0 * w00 + v1 * w10;
                p1[i * 2 + 0] += v0 * w01 + v1 * w11;
                p0[i * 2 + 1] += v2 * w00 + v3 * w10;
                p1[i * 2 + 1] += v2 * w01 + v3 * w11;
            }
        }
#pragma unroll
        for (int off = 1; off <= 2; off <<= 1) {
#pragma unroll
            for (int k = 0; k < 4; k++) {
                p0[k] += __shfl_xor_sync(0xFFFFFFFFu, p0[k], off);
                p1[k] += __shfl_xor_sync(0xFFFFFFFFu, p1[k], off);
            }
        }
        if ((lane & 3) == 0) {
#pragma unroll
            for (int k = 0; k < 4; k++) {
                int row = wm * 32 + (k >> 1) * 16 + qrow + (k & 1) * 8;
                sred[wn][row][0] = p0[k];
                sred[wn][row][1] = p1[k];
            }
        }
        __syncthreads();
        if (tid < 128) {
            int gr = row0 + tid;
            if (gr < M) {
                float l0 = b_o2[0] + sred[0][tid][0] + sred[1][tid][0];
                float l1 = b_o2[1] + sred[0][tid][1] + sred[1][tid][1];
                float m = fmaxf(l0, l1);
                float e0 = __expf(l0 - m), e1 = __expf(l1 - m);
                float inv = 1.f / (e0 + e1);
                outp[(size_t)gr * 2] = e0 * inv;
                outp[(size_t)gr * 2 + 1] = e1 * inv;
            }
        }
    }
}

// ------------------------- Aggregation (bf16, warp/segment — R10 exact) ----

__global__ void aggregate_kernel(__nv_bfloat16* __restrict__ buf,
                                 const int* __restrict__ seg_start,
                                 const int* __restrict__ cnt,
                                 const int* __restrict__ perm, int NR) {
    int w = blockIdx.x * (blockDim.x >> 5) + (threadIdx.x >> 5);
    if (w >= NR) return;
    int lane = threadIdx.x & 31;
    int start = seg_start[w];
    int deg = cnt[w];
    int end = start + deg;
    float a0 = 0.f, a1 = 0.f, a2 = 0.f, a3 = 0.f;
    int e = start;
    for (; e + 3 < end; e += 4) {
        int s0 = perm[e], s1 = perm[e + 1], s2 = perm[e + 2], s3 = perm[e + 3];
        uint2 v0 = *(const uint2*)(buf + (size_t)s0 * 384 + lane * 4);
        uint2 v1 = *(const uint2*)(buf + (size_t)s1 * 384 + lane * 4);
        uint2 v2 = *(const uint2*)(buf + (size_t)s2 * 384 + lane * 4);
        uint2 v3 = *(const uint2*)(buf + (size_t)s3 * 384 + lane * 4);
#define ACCUM(v)                                                              \
        {                                                                     \
            float2 f0 = __bfloat1622float2(*(__nv_bfloat162*)&(v).x);         \
            float2 f1 = __bfloat1622float2(*(__nv_bfloat162*)&(v).y);         \
            a0 += f0.x; a1 += f0.y; a2 += f1.x; a3 += f1.y;                   \
        }
        ACCUM(v0) ACCUM(v1) ACCUM(v2) ACCUM(v3)
    }
    for (; e < end; e++) {
        int s = perm[e];
        uint2 v = *(const uint2*)(buf + (size_t)s * 384 + lane * 4);
        ACCUM(v)
    }
#undef ACCUM
    float inv = 1.f / (float)max(deg, 1);
    __nv_bfloat162 h0 = __floats2bfloat162_rn(a0 * inv, a1 * inv);
    __nv_bfloat162 h1 = __floats2bfloat162_rn(a2 * inv, a3 * inv);
    uint2 outv;
    outv.x = *(uint32_t*)&h0;
    outv.y = *(uint32_t*)&h1;
    int node = w >> 1, r = w & 1;
    *(uint2*)(buf + (size_t)node * 384 + 128 + r * 128 + lane * 4) = outv;
}

// ------------------------- Launch ------------------------------------------

extern "C" void kernel_launch(void* const* d_in, const int* in_sizes, int n_in,
                              void* d_out, int out_size) {
    const float* des     = (const float*)d_in[0];
    const float* tweet   = (const float*)d_in[1];
    const float* prop    = (const float*)d_in[2];
    const int*   eidx    = (const int*)d_in[3];
    const int*   etype   = (const int*)d_in[4];
    const float* W_des   = (const float*)d_in[5];
    const float* b_des   = (const float*)d_in[6];
    const float* W_tweet = (const float*)d_in[7];
    const float* b_tweet = (const float*)d_in[8];
    const float* W_prop  = (const float*)d_in[9];
    const float* b_prop  = (const float*)d_in[10];
    const float* W_in    = (const float*)d_in[11];
    const float* b_in    = (const float*)d_in[12];
    const float* W_rel   = (const float*)d_in[13];
    const float* W_root  = (const float*)d_in[14];
    const float* b_rgcn  = (const float*)d_in[15];
    const float* W_o1    = (const float*)d_in[16];
    const float* b_o1    = (const float*)d_in[17];
    const float* W_o2    = (const float*)d_in[18];
    const float* b_o2    = (const float*)d_in[19];

    const int N = in_sizes[0] / 768;
    const int E = in_sizes[4];
    const int NR = N * 2;
    const int* src = eidx;
    const int* dst = eidx + E;

    __nv_bfloat16 *A, *B, *Wt_des, *Wt_tweet, *Wt_prop, *Wt_in, *Wt_cat, *Wt_o1;
    cudaGetSymbolAddress((void**)&A, g_A);
    cudaGetSymbolAddress((void**)&B, g_B);
    cudaGetSymbolAddress((void**)&Wt_des, g_Wt_des);
    cudaGetSymbolAddress((void**)&Wt_tweet, g_Wt_tweet);
    cudaGetSymbolAddress((void**)&Wt_prop, g_Wt_prop);
    cudaGetSymbolAddress((void**)&Wt_in, g_Wt_in);
    cudaGetSymbolAddress((void**)&Wt_cat, g_Wt_cat);
    cudaGetSymbolAddress((void**)&Wt_o1, g_Wt_o1);
    int *perm, *seg_start, *cntcur;
    cudaGetSymbolAddress((void**)&perm, g_perm);
    cudaGetSymbolAddress((void**)&seg_start, g_seg_start);
    cudaGetSymbolAddress((void**)&cntcur, g_cntcur);
    int* cnt = cntcur;
    int* cursor = cntcur + NRSEG;
    int* total = cntcur + 2 * NRSEG;

    const int gm = (N + 127) / 128;
    const int ncnt = 2048;
    const int nplace = 1024;

    // launch 1: zero cnt + cursor + total in one memset
    cudaMemsetAsync(cntcur, 0, (size_t)(2 * NRSEG + 1) * sizeof(int));
    // launch 2: weight prep
    prep_kernel<<<(PREP_TOTAL + 255) / 256, 256>>>(
        W_des, W_tweet, W_prop, W_in, W_o1, W_root, W_rel, Wt_des, Wt_tweet,
        Wt_prop, Wt_in, Wt_o1, Wt_cat);
    // launch 3: encoders + CSR count
    gemm_enc3_count<<<ncnt + gm * 3, 128>>>(des, tweet, prop, Wt_des, Wt_tweet,
                                            Wt_prop, b_des, b_tweet, b_prop, B,
                                            N, gm, dst, etype, E, cnt, ncnt);
    // launch 4: segment offsets (unordered CSR)
    seg_offsets_kernel<<<(NR + 1023) / 1024, 1024>>>(cnt, seg_start, total, NR);
    // launch 5 (ncu sample): cat96 @ W_in -> A cols 0..127, fused with place
    gemm_mma<false, true><<<nplace + gm, 256>>>(
        B, 384, Wt_in, 128, b_in, A, 384, N, 96, 1, nullptr, nullptr, nullptr,
        src, dst, etype, E, seg_start, cursor, perm, nplace);
    // launch 6: aggregate layer 1
    aggregate_kernel<<<(NR + 7) / 8, 256>>>(A, seg_start, cnt, perm, NR);
    // launch 7: rgcn layer 1 GEMM
    gemm_mma<false, false><<<gm, 256>>>(A, 384, Wt_cat, 384, b_rgcn, B, 384, N,
                                        384, 0, nullptr, nullptr, nullptr,
                                        nullptr, nullptr, nullptr, 0, nullptr,
                                        nullptr, nullptr, 0);
    // launch 8: aggregate layer 2
    aggregate_kernel<<<(NR + 7) / 8, 256>>>(B, seg_start, cnt, perm, NR);
    // launch 9: rgcn layer 2 GEMM
    gemm_mma<false, false><<<gm, 256>>>(B, 384, Wt_cat, 384, b_rgcn, A, 384, N,
                                        384, 0, nullptr, nullptr, nullptr,
                                        nullptr, nullptr, nullptr, 0, nullptr,
                                        nullptr, nullptr, 0);
    // launch 10: head
    gemm_mma<true, false><<<gm, 256>>>(A, 384, Wt_o1, 128, b_o1, nullptr, 384,
                                       N, 128, 1, W_o2, b_o2, (float*)d_out,
                                       nullptr, nullptr, nullptr, 0, nullptr,
                                       nullptr, nullptr, 0);
}

// round 16
// speedup vs baseline: 1.5232x; 1.0106x over previous
#include <cuda_runtime.h>
#include <cuda_bf16.h>
#include <cstdint>

// ---------------------------------------------------------------------------
// BotRGCN on GB300 — bf16 mma.sync (m16n8k16) pipeline.
//   rgcn(x) = [x | mean_0(x) | mean_1(x)] @ [W_root; W_rel0; W_rel1] + b
// R16: R15 (528.9us, cp.async 2-stage) + ONE change: pipeline deepened to
// 3 stages (prefill 2, CP_WAIT(2)) to hide two chunk-latencies in the
// K>=128 GEMMs. smem 60KB/CTA (2 CTAs/SM preserved), regs unchanged.
// ---------------------------------------------------------------------------

#define MAXN 100000
#define MAXE 3200000
#define NRSEG (MAXN * 2)

__device__ __align__(256) __nv_bfloat16 g_A[(size_t)MAXN * 384];
__device__ __align__(256) __nv_bfloat16 g_B[(size_t)MAXN * 384];
__device__ __align__(256) __nv_bfloat16 g_Wt_des[32 * 768];
__device__ __align__(256) __nv_bfloat16 g_Wt_tweet[32 * 768];
__device__ __align__(256) __nv_bfloat16 g_Wt_prop[32 * 64];
__device__ __align__(256) __nv_bfloat16 g_Wt_in[128 * 128];
__device__ __align__(256) __nv_bfloat16 g_Wt_cat[128 * 384];
__device__ __align__(256) __nv_bfloat16 g_Wt_o1[128 * 128];
__device__ __align__(256) int g_perm[MAXE];
__device__ __align__(256) int g_seg_start[NRSEG];
// cnt | cursor | total : one contiguous region, zeroed by a single memset
__device__ __align__(256) int g_cntcur[2 * NRSEG + 1];

__device__ __forceinline__ uint32_t smem_u32(const void* p) {
    uint32_t a;
    asm("{ .reg .u64 t; cvta.to.shared.u64 t, %1; cvt.u32.u64 %0, t; }"
        : "=r"(a) : "l"(p));
    return a;
}

#define CP_ASYNC16(dst, src, srcbytes)                                        \
    asm volatile("cp.async.cg.shared.global [%0], [%1], 16, %2;"              \
                 :: "r"(dst), "l"(src), "r"(srcbytes))
#define CP_COMMIT() asm volatile("cp.async.commit_group;" ::: "memory")
#define CP_WAIT(n) asm volatile("cp.async.wait_group %0;" :: "n"(n) : "memory")

// ------------------------- segment offsets (unordered CSR) -----------------

__global__ void seg_offsets_kernel(const int* __restrict__ cnt,
                                   int* __restrict__ seg_start,
                                   int* __restrict__ total, int n) {
    __shared__ int s[1024];
    __shared__ int base;
    int idx = blockIdx.x * 1024 + threadIdx.x;
    int v = (idx < n) ? cnt[idx] : 0;
    s[threadIdx.x] = v;
    __syncthreads();
    for (int off = 1; off < 1024; off <<= 1) {
        int t = (threadIdx.x >= off) ? s[threadIdx.x - off] : 0;
        __syncthreads();
        s[threadIdx.x] += t;
        __syncthreads();
    }
    if (threadIdx.x == 1023) base = atomicAdd(total, s[1023]);
    __syncthreads();
    if (idx < n) seg_start[idx] = base + s[threadIdx.x] - v;
}

// ------------------------- Weight prep (single launch) ---------------------

__device__ __forceinline__ void tr_one(const float* in, __nv_bfloat16* out,
                                       int idx, int K, int Nw, int Kpad) {
    int n = idx / Kpad, k = idx % Kpad;
    out[idx] = (k < K) ? __float2bfloat16_rn(in[k * Nw + n])
                       : __float2bfloat16_rn(0.f);
}

#define PREP_TOTAL (24576 + 24576 + 2048 + 16384 + 16384 + 49152)

__global__ void prep_kernel(const float* __restrict__ W_des,
                            const float* __restrict__ W_tweet,
                            const float* __restrict__ W_prop,
                            const float* __restrict__ W_in,
                            const float* __restrict__ W_o1,
                            const float* __restrict__ W_root,
                            const float* __restrict__ W_rel,
                            __nv_bfloat16* __restrict__ Wt_des,
                            __nv_bfloat16* __restrict__ Wt_tweet,
                            __nv_bfloat16* __restrict__ Wt_prop,
                            __nv_bfloat16* __restrict__ Wt_in,
                            __nv_bfloat16* __restrict__ Wt_o1,
                            __nv_bfloat16* __restrict__ Wt_cat) {
    int idx = blockIdx.x * blockDim.x + threadIdx.x;
    if (idx < 24576) {
        tr_one(W_des, Wt_des, idx, 768, 32, 768);
    } else if ((idx -= 24576) < 24576) {
        tr_one(W_tweet, Wt_tweet, idx, 768, 32, 768);
    } else if ((idx -= 24576) < 2048) {
        tr_one(W_prop, Wt_prop, idx, 14, 32, 64);
    } else if ((idx -= 2048) < 16384) {
        tr_one(W_in, Wt_in, idx, 96, 128, 128);
    } else if ((idx -= 16384) < 16384) {
        tr_one(W_o1, Wt_o1, idx, 128, 128, 128);
    } else if ((idx -= 16384) < 49152) {
        int n = idx / 384, k = idx % 384;
        float v = (k < 128) ? W_root[k * 128 + n] : W_rel[(k - 128) * 128 + n];
        Wt_cat[idx] = __float2bfloat16_rn(v);
    }
}

// ------------------------- mma primitives ----------------------------------

#define LDMX4(r0, r1, r2, r3, addr)                                           \
    asm volatile("ldmatrix.sync.aligned.m8n8.x4.shared.b16 {%0,%1,%2,%3}, [%4];" \
                 : "=r"(r0), "=r"(r1), "=r"(r2), "=r"(r3) : "r"(addr))
#define LDMX2(r0, r1, addr)                                                   \
    asm volatile("ldmatrix.sync.aligned.m8n8.x2.shared.b16 {%0,%1}, [%2];"    \
                 : "=r"(r0), "=r"(r1) : "r"(addr))
#define MMA16816(c, a, b)                                                     \
    asm volatile(                                                             \
        "mma.sync.aligned.m16n8k16.row.col.f32.bf16.bf16.f32 "                \
        "{%0,%1,%2,%3}, {%4,%5,%6,%7}, {%8,%9}, {%0,%1,%2,%3};"               \
        : "+f"((c)[0]), "+f"((c)[1]), "+f"((c)[2]), "+f"((c)[3])              \
        : "r"((a)[0]), "r"((a)[1]), "r"((a)[2]), "r"((a)[3]),                 \
          "r"((b)[0]), "r"((b)[1]))

// ------------------------- fused encoder GEMM + edge count ------------------
// Blocks [0, ncnt): CSR count (grid-stride histogram).
// Blocks [ncnt, ncnt + 3*gm): encoder slices (des | tweet | prop).

__global__ void __launch_bounds__(128) gemm_enc3_count(
    const float* __restrict__ des, const float* __restrict__ tweet,
    const float* __restrict__ prop,
    const __nv_bfloat16* __restrict__ Wt_des,
    const __nv_bfloat16* __restrict__ Wt_tweet,
    const __nv_bfloat16* __restrict__ Wt_prop,
    const float* __restrict__ b_des, const float* __restrict__ b_tweet,
    const float* __restrict__ b_prop, __nv_bfloat16* __restrict__ Bout,
    int M, int gm,
    const int* __restrict__ dstE, const int* __restrict__ etE, int E,
    int* __restrict__ cnt, int ncnt) {
    if (blockIdx.x < (unsigned)ncnt) {
        for (int i = blockIdx.x * 128 + threadIdx.x; i < E; i += ncnt * 128)
            atomicAdd(&cnt[dstE[i] * 2 + etE[i]], 1);
        return;
    }
    const int flat = blockIdx.x - ncnt;
    const int bx = flat % gm, by = flat / gm;

    const float* A;
    const __nv_bfloat16* Wt;
    const float* bias;
    __nv_bfloat16* C;
    int lda, K, ldw;
    if (by == 0) {
        A = des; Wt = Wt_des; bias = b_des; C = Bout; lda = 768; K = 768; ldw = 768;
    } else if (by == 1) {
        A = tweet; Wt = Wt_tweet; bias = b_tweet; C = Bout + 32; lda = 768; K = 768; ldw = 768;
    } else {
        A = prop; Wt = Wt_prop; bias = b_prop; C = Bout + 64; lda = 14; K = 14; ldw = 64;
    }
    const int ldc = 384;

    constexpr int STR = 40;
    __shared__ __nv_bfloat16 sA[128 * STR];
    __shared__ __nv_bfloat16 sB[32 * STR];

    const int tid = threadIdx.x;
    const int wid = tid >> 5, lane = tid & 31;
    const int row0 = bx * 128;
    const uint32_t baseA = smem_u32(sA);
    const uint32_t baseB = smem_u32(sB);

    float acc[2][4][4];
#pragma unroll
    for (int i = 0; i < 2; i++)
#pragma unroll
        for (int j = 0; j < 4; j++)
#pragma unroll
            for (int q = 0; q < 4; q++) acc[i][j][q] = 0.f;

    uint32_t aAddr[2];
#pragma unroll
    for (int i = 0; i < 2; i++)
        aAddr[i] = baseA + (uint32_t)(((wid * 32 + i * 16 + (lane & 15)) * STR +
                                       ((lane >> 4) * 8)) * 2);
    uint32_t bAddr[4];
#pragma unroll
    for (int j = 0; j < 4; j++)
        bAddr[j] = baseB + (uint32_t)(((j * 8 + (lane & 7)) * STR +
                                       (((lane >> 3) & 1) * 8)) * 2);

    const int nchunks = (K + 31) >> 5;
    for (int c = 0; c < nchunks; c++) {
        const int k0 = c << 5;
#pragma unroll 2
        for (int idx = tid; idx < 128 * 4; idx += 128) {
            int r = idx >> 2, g = idx & 3;
            int gr = row0 + r, gc0 = k0 + g * 8;
            uint4 val;
            if (gr < M && gc0 + 7 < K && (lda & 3) == 0) {
                const float4* p = (const float4*)(A + (size_t)gr * lda + gc0);
                float4 v0 = p[0], v1 = p[1];
                __nv_bfloat162 h0 = __floats2bfloat162_rn(v0.x, v0.y);
                __nv_bfloat162 h1 = __floats2bfloat162_rn(v0.z, v0.w);
                __nv_bfloat162 h2 = __floats2bfloat162_rn(v1.x, v1.y);
                __nv_bfloat162 h3 = __floats2bfloat162_rn(v1.z, v1.w);
                val.x = *(uint32_t*)&h0; val.y = *(uint32_t*)&h1;
                val.z = *(uint32_t*)&h2; val.w = *(uint32_t*)&h3;
            } else {
                float v[8];
#pragma unroll
                for (int e = 0; e < 8; e++) {
                    int gc = gc0 + e;
                    v[e] = (gr < M && gc < K) ? A[(size_t)gr * lda + gc] : 0.f;
                }
                __nv_bfloat162 h0 = __floats2bfloat162_rn(v[0], v[1]);
                __nv_bfloat162 h1 = __floats2bfloat162_rn(v[2], v[3]);
                __nv_bfloat162 h2 = __floats2bfloat162_rn(v[4], v[5]);
                __nv_bfloat162 h3 = __floats2bfloat162_rn(v[6], v[7]);
                val.x = *(uint32_t*)&h0; val.y = *(uint32_t*)&h1;
                val.z = *(uint32_t*)&h2; val.w = *(uint32_t*)&h3;
            }
            *(uint4*)(sA + r * STR + g * 8) = val;
        }
        {
            int n = tid >> 2, g = tid & 3;
            uint4 val = *(const uint4*)(Wt + (size_t)n * ldw + k0 + g * 8);
            *(uint4*)(sB + n * STR + g * 8) = val;
        }
        __syncthreads();

#pragma unroll
        for (int s = 0; s < 2; s++) {
            uint32_t bfr[4][2];
#pragma unroll
            for (int j = 0; j < 4; j++)
                LDMX2(bfr[j][0], bfr[j][1], bAddr[j] + s * 32);
#pragma unroll
            for (int i = 0; i < 2; i++) {
                uint32_t afr[4];
                LDMX4(afr[0], afr[1], afr[2], afr[3], aAddr[i] + s * 32);
#pragma unroll
                for (int j = 0; j < 4; j++) MMA16816(acc[i][j], afr, bfr[j]);
            }
        }
        __syncthreads();
    }

    const int qrow = lane >> 2, qcol = (lane & 3) * 2;
#pragma unroll
    for (int i = 0; i < 2; i++) {
#pragma unroll
        for (int j = 0; j < 4; j++) {
            int gc = j * 8 + qcol;
            float b0 = bias[gc], b1 = bias[gc + 1];
            int gr0 = row0 + wid * 32 + i * 16 + qrow;
            float v0 = acc[i][j][0] + b0, v1 = acc[i][j][1] + b1;
            float v2 = acc[i][j][2] + b0, v3 = acc[i][j][3] + b1;
            v0 = (v0 >= 0.f) ? v0 : 0.01f * v0;
            v1 = (v1 >= 0.f) ? v1 : 0.01f * v1;
            v2 = (v2 >= 0.f) ? v2 : 0.01f * v2;
            v3 = (v3 >= 0.f) ? v3 : 0.01f * v3;
            if (gr0 < M) {
                __nv_bfloat162 h = __floats2bfloat162_rn(v0, v1);
                *(uint32_t*)(C + (size_t)gr0 * ldc + gc) = *(uint32_t*)&h;
            }
            if (gr0 + 8 < M) {
                __nv_bfloat162 h = __floats2bfloat162_rn(v2, v3);
                *(uint32_t*)(C + (size_t)(gr0 + 8) * ldc + gc) = *(uint32_t*)&h;
            }
        }
    }
}

// ------------------------- main GEMM (bf16 A, cp.async 3-stage) ------------
// C[M,128](bf16, ldc) = act( A[M,K](bf16) @ Wt[128,K]^T + bias )
// BM=128, BN=128, BK=32; 8 warps (4x2), warp tile 32x64; triple-buffered
// smem via cp.async (prefill 2 chunks; steady-state waits leave 2 in flight).
// HEAD: softmax(lrelu(acc+bias) @ W_o2 + b_o2) -> fp32 [M,2].
// PLACE: blocks [0, nplace) run CSR place instead (fused independent work).

template <bool HEAD, bool PLACE>
__global__ void __launch_bounds__(256) gemm_mma(
    const __nv_bfloat16* __restrict__ Aptr, int lda,
    const __nv_bfloat16* __restrict__ Wt, int ldw,
    const float* __restrict__ bias, __nv_bfloat16* __restrict__ C, int ldc,
    int M, int K, int act,
    const float* __restrict__ W_o2, const float* __restrict__ b_o2,
    float* __restrict__ outp,
    const int* __restrict__ srcE, const int* __restrict__ dstE,
    const int* __restrict__ etE, int E, const int* __restrict__ seg_start,
    int* __restrict__ cursor, int* __restrict__ perm, int nplace) {
    if (PLACE) {
        if (blockIdx.x < (unsigned)nplace) {
            for (int i = blockIdx.x * 256 + threadIdx.x; i < E;
                 i += nplace * 256) {
                int seg = dstE[i] * 2 + etE[i];
                int p = atomicAdd(&cursor[seg], 1);
                perm[seg_start[seg] + p] = srcE[i];
            }
            return;
        }
    }
    const int bx = PLACE ? (blockIdx.x - nplace) : blockIdx.x;

    constexpr int BN = 128;
    constexpr int THREADS = 256;
    constexpr int WN = 64;
    constexpr int NATOMS = 8;
    constexpr int STR = 40;
    constexpr int STAGES = 3;
    constexpr uint32_t ABUF = 128 * STR * 2;  // bytes per buffer (A and B equal)

    __shared__ __nv_bfloat16 smem[(STAGES * 128 + STAGES * BN) * STR];

    const int tid = threadIdx.x;
    const int wid = tid >> 5, lane = tid & 31;
    const int wm = wid & 3, wn = wid >> 2;
    const int row0 = bx * 128;
    const uint32_t base = smem_u32(smem);
    const uint32_t baseA = base;                   // A0..A2
    const uint32_t baseB = base + STAGES * ABUF;   // B0..B2

    float acc[2][NATOMS][4];
#pragma unroll
    for (int i = 0; i < 2; i++)
#pragma unroll
        for (int j = 0; j < NATOMS; j++)
#pragma unroll
            for (int q = 0; q < 4; q++) acc[i][j][q] = 0.f;

    uint32_t aAddr[2];
#pragma unroll
    for (int i = 0; i < 2; i++)
        aAddr[i] = baseA + (uint32_t)(((wm * 32 + i * 16 + (lane & 15)) * STR +
                                       ((lane >> 4) * 8)) * 2);
    uint32_t bAddr[NATOMS];
#pragma unroll
    for (int j = 0; j < NATOMS; j++)
        bAddr[j] = baseB + (uint32_t)(((wn * WN + j * 8 + (lane & 7)) * STR +
                                       (((lane >> 3) & 1) * 8)) * 2);

    const int nchunks = (K + 31) >> 5;

    auto issue = [&](int c) {
        const int k0 = c << 5;
        const uint32_t st = (uint32_t)(c % STAGES);
        const uint32_t dA = baseA + st * ABUF;
        const uint32_t dB = baseB + st * ABUF;
#pragma unroll
        for (int it = 0; it < 2; it++) {
            int idx = tid + it * THREADS;   // 0..511
            int r = idx >> 2, g = idx & 3;
            int gr = row0 + r;
            int ok = (gr < M) ? 16 : 0;
            const __nv_bfloat16* src =
                Aptr + (size_t)(ok ? gr : 0) * lda + k0 + g * 8;
            CP_ASYNC16(dA + (uint32_t)((r * STR + g * 8) * 2), src, ok);
        }
#pragma unroll
        for (int it = 0; it < 2; it++) {
            int idx = tid + it * THREADS;
            int r = idx >> 2, g = idx & 3;
            const __nv_bfloat16* src = Wt + (size_t)r * ldw + k0 + g * 8;
            CP_ASYNC16(dB + (uint32_t)((r * STR + g * 8) * 2), src, 16);
        }
        CP_COMMIT();
    };

    issue(0);
    if (nchunks > 1) issue(1);
    for (int c = 0; c < nchunks; c++) {
        if (c + 2 < nchunks) {
            issue(c + 2);
            CP_WAIT(2);
        } else if (c + 1 < nchunks) {
            CP_WAIT(1);
        } else {
            CP_WAIT(0);
        }
        __syncthreads();

        const uint32_t boff = (uint32_t)(c % STAGES) * ABUF;
#pragma unroll
        for (int s = 0; s < 2; s++) {
            uint32_t bfr[NATOMS][2];
#pragma unroll
            for (int j = 0; j < NATOMS; j++)
                LDMX2(bfr[j][0], bfr[j][1], bAddr[j] + boff + s * 32);
#pragma unroll
            for (int i = 0; i < 2; i++) {
                uint32_t afr[4];
                LDMX4(afr[0], afr[1], afr[2], afr[3], aAddr[i] + boff + s * 32);
#pragma unroll
                for (int j = 0; j < NATOMS; j++) MMA16816(acc[i][j], afr, bfr[j]);
            }
        }
        __syncthreads();
    }

    const int qrow = lane >> 2, qcol = (lane & 3) * 2;

    if (!HEAD) {
#pragma unroll
        for (int i = 0; i < 2; i++) {
#pragma unroll
            for (int j = 0; j < NATOMS; j++) {
                int gc = wn * WN + j * 8 + qcol;
                float b0 = bias[gc], b1 = bias[gc + 1];
                int gr0 = row0 + wm * 32 + i * 16 + qrow;
                float v0 = acc[i][j][0] + b0, v1 = acc[i][j][1] + b1;
                float v2 = acc[i][j][2] + b0, v3 = acc[i][j][3] + b1;
                if (act) {
                    v0 = (v0 >= 0.f) ? v0 : 0.01f * v0;
                    v1 = (v1 >= 0.f) ? v1 : 0.01f * v1;
                    v2 = (v2 >= 0.f) ? v2 : 0.01f * v2;
                    v3 = (v3 >= 0.f) ? v3 : 0.01f * v3;
                }
                if (gr0 < M) {
                    __nv_bfloat162 h = __floats2bfloat162_rn(v0, v1);
                    *(uint32_t*)(C + (size_t)gr0 * ldc + gc) = *(uint32_t*)&h;
                }
                if (gr0 + 8 < M) {
                    __nv_bfloat162 h = __floats2bfloat162_rn(v2, v3);
                    *(uint32_t*)(C + (size_t)(gr0 + 8) * ldc + gc) = *(uint32_t*)&h;
                }
            }
        }
    } else {
        __shared__ float sred[2][128][2];
        float p0[4] = {0.f, 0.f, 0.f, 0.f};
        float p1[4] = {0.f, 0.f, 0.f, 0.f};
#pragma unroll
        for (int i = 0; i < 2; i++) {
#pragma unroll
            for (int j = 0; j < NATOMS; j++) {
                int gc = wn * WN + j * 8 + qcol;
                float b0 = bias[gc], b1 = bias[gc + 1];
                float v0 = acc[i][j][0] + b0, v1 = acc[i][j][1] + b1;
                float v2 = acc[i][j][2] + b0, v3 = acc[i][j][3] + b1;
                v0 = (v0 >= 0.f) ? v0 : 0.01f * v0;
                v1 = (v1 >= 0.f) ? v1 : 0.01f * v1;
                v2 = (v2 >= 0.f) ? v2 : 0.01f * v2;
                v3 = (v3 >= 0.f) ? v3 : 0.01f * v3;
                float w00 = W_o2[gc * 2], w01 = W_o2[gc * 2 + 1];
                float w10 = W_o2[(gc + 1) * 2], w11 = W_o2[(gc + 1) * 2 + 1];
                p0[i * 2 + 0] += v0 * w00 + v1 * w10;
                p1[i * 2 + 0] += v0 * w01 + v1 * w11;
                p0[i * 2 + 1] += v2 * w00 + v3 * w10;
                p1[i * 2 + 1] += v2 * w01 + v3 * w11;
            }
        }
#pragma unroll
        for (int off = 1; off <= 2; off <<= 1) {
#pragma unroll
            for (int k = 0; k < 4; k++) {
                p0[k] += __shfl_xor_sync(0xFFFFFFFFu, p0[k], off);
                p1[k] += __shfl_xor_sync(0xFFFFFFFFu, p1[k], off);
            }
        }
        if ((lane & 3) == 0) {
#pragma unroll
            for (int k = 0; k < 4; k++) {
                int row = wm * 32 + (k >> 1) * 16 + qrow + (k & 1) * 8;
                sred[wn][row][0] = p0[k];
                sred[wn][row][1] = p1[k];
            }
        }
        __syncthreads();
        if (tid < 128) {
            int gr = row0 + tid;
            if (gr < M) {
                float l0 = b_o2[0] + sred[0][tid][0] + sred[1][tid][0];
                float l1 = b_o2[1] + sred[0][tid][1] + sred[1][tid][1];
                float m = fmaxf(l0, l1);
                float e0 = __expf(l0 - m), e1 = __expf(l1 - m);
                float inv = 1.f / (e0 + e1);
                outp[(size_t)gr * 2] = e0 * inv;
                outp[(size_t)gr * 2 + 1] = e1 * inv;
            }
        }
    }
}

// ------------------------- Aggregation (bf16, warp/segment — R10 exact) ----

__global__ void aggregate_kernel(__nv_bfloat16* __restrict__ buf,
                                 const int* __restrict__ seg_start,
                                 const int* __restrict__ cnt,
                                 const int* __restrict__ perm, int NR) {
    int w = blockIdx.x * (blockDim.x >> 5) + (threadIdx.x >> 5);
    if (w >= NR) return;
    int lane = threadIdx.x & 31;
    int start = seg_start[w];
    int deg = cnt[w];
    int end = start + deg;
    float a0 = 0.f, a1 = 0.f, a2 = 0.f, a3 = 0.f;
    int e = start;
    for (; e + 3 < end; e += 4) {
        int s0 = perm[e], s1 = perm[e + 1], s2 = perm[e + 2], s3 = perm[e + 3];
        uint2 v0 = *(const uint2*)(buf + (size_t)s0 * 384 + lane * 4);
        uint2 v1 = *(const uint2*)(buf + (size_t)s1 * 384 + lane * 4);
        uint2 v2 = *(const uint2*)(buf + (size_t)s2 * 384 + lane * 4);
        uint2 v3 = *(const uint2*)(buf + (size_t)s3 * 384 + lane * 4);
#define ACCUM(v)                                                              \
        {                                                                     \
            float2 f0 = __bfloat1622float2(*(__nv_bfloat162*)&(v).x);         \
            float2 f1 = __bfloat1622float2(*(__nv_bfloat162*)&(v).y);         \
            a0 += f0.x; a1 += f0.y; a2 += f1.x; a3 += f1.y;                   \
        }
        ACCUM(v0) ACCUM(v1) ACCUM(v2) ACCUM(v3)
    }
    for (; e < end; e++) {
        int s = perm[e];
        uint2 v = *(const uint2*)(buf + (size_t)s * 384 + lane * 4);
        ACCUM(v)
    }
#undef ACCUM
    float inv = 1.f / (float)max(deg, 1);
    __nv_bfloat162 h0 = __floats2bfloat162_rn(a0 * inv, a1 * inv);
    __nv_bfloat162 h1 = __floats2bfloat162_rn(a2 * inv, a3 * inv);
    uint2 outv;
    outv.x = *(uint32_t*)&h0;
    outv.y = *(uint32_t*)&h1;
    int node = w >> 1, r = w & 1;
    *(uint2*)(buf + (size_t)node * 384 + 128 + r * 128 + lane * 4) = outv;
}

// ------------------------- Launch ------------------------------------------

extern "C" void kernel_launch(void* const* d_in, const int* in_sizes, int n_in,
                              void* d_out, int out_size) {
    const float* des     = (const float*)d_in[0];
    const float* tweet   = (const float*)d_in[1];
    const float* prop    = (const float*)d_in[2];
    const int*   eidx    = (const int*)d_in[3];
    const int*   etype   = (const int*)d_in[4];
    const float* W_des   = (const float*)d_in[5];
    const float* b_des   = (const float*)d_in[6];
    const float* W_tweet = (const float*)d_in[7];
    const float* b_tweet = (const float*)d_in[8];
    const float* W_prop  = (const float*)d_in[9];
    const float* b_prop  = (const float*)d_in[10];
    const float* W_in    = (const float*)d_in[11];
    const float* b_in    = (const float*)d_in[12];
    const float* W_rel   = (const float*)d_in[13];
    const float* W_root  = (const float*)d_in[14];
    const float* b_rgcn  = (const float*)d_in[15];
    const float* W_o1    = (const float*)d_in[16];
    const float* b_o1    = (const float*)d_in[17];
    const float* W_o2    = (const float*)d_in[18];
    const float* b_o2    = (const float*)d_in[19];

    const int N = in_sizes[0] / 768;
    const int E = in_sizes[4];
    const int NR = N * 2;
    const int* src = eidx;
    const int* dst = eidx + E;

    __nv_bfloat16 *A, *B, *Wt_des, *Wt_tweet, *Wt_prop, *Wt_in, *Wt_cat, *Wt_o1;
    cudaGetSymbolAddress((void**)&A, g_A);
    cudaGetSymbolAddress((void**)&B, g_B);
    cudaGetSymbolAddress((void**)&Wt_des, g_Wt_des);
    cudaGetSymbolAddress((void**)&Wt_tweet, g_Wt_tweet);
    cudaGetSymbolAddress((void**)&Wt_prop, g_Wt_prop);
    cudaGetSymbolAddress((void**)&Wt_in, g_Wt_in);
    cudaGetSymbolAddress((void**)&Wt_cat, g_Wt_cat);
    cudaGetSymbolAddress((void**)&Wt_o1, g_Wt_o1);
    int *perm, *seg_start, *cntcur;
    cudaGetSymbolAddress((void**)&perm, g_perm);
    cudaGetSymbolAddress((void**)&seg_start, g_seg_start);
    cudaGetSymbolAddress((void**)&cntcur, g_cntcur);
    int* cnt = cntcur;
    int* cursor = cntcur + NRSEG;
    int* total = cntcur + 2 * NRSEG;

    const int gm = (N + 127) / 128;
    const int ncnt = 2048;
    const int nplace = 1024;

    // launch 1: zero cnt + cursor + total in one memset
    cudaMemsetAsync(cntcur, 0, (size_t)(2 * NRSEG + 1) * sizeof(int));
    // launch 2: weight prep
    prep_kernel<<<(PREP_TOTAL + 255) / 256, 256>>>(
        W_des, W_tweet, W_prop, W_in, W_o1, W_root, W_rel, Wt_des, Wt_tweet,
        Wt_prop, Wt_in, Wt_o1, Wt_cat);
    // launch 3: encoders + CSR count
    gemm_enc3_count<<<ncnt + gm * 3, 128>>>(des, tweet, prop, Wt_des, Wt_tweet,
                                            Wt_prop, b_des, b_tweet, b_prop, B,
                                            N, gm, dst, etype, E, cnt, ncnt);
    // launch 4: segment offsets (unordered CSR)
    seg_offsets_kernel<<<(NR + 1023) / 1024, 1024>>>(cnt, seg_start, total, NR);
    // launch 5 (ncu sample): cat96 @ W_in -> A cols 0..127, fused with place
    gemm_mma<false, true><<<nplace + gm, 256>>>(
        B, 384, Wt_in, 128, b_in, A, 384, N, 96, 1, nullptr, nullptr, nullptr,
        src, dst, etype, E, seg_start, cursor, perm, nplace);
    // launch 6: aggregate layer 1
    aggregate_kernel<<<(NR + 7) / 8, 256>>>(A, seg_start, cnt, perm, NR);
    // launch 7: rgcn layer 1 GEMM
    gemm_mma<false, false><<<gm, 256>>>(A, 384, Wt_cat, 384, b_rgcn, B, 384, N,
                                        384, 0, nullptr, nullptr, nullptr,
                                        nullptr, nullptr, nullptr, 0, nullptr,
                                        nullptr, nullptr, 0);
    // launch 8: aggregate layer 2
    aggregate_kernel<<<(NR + 7) / 8, 256>>>(B, seg_start, cnt, perm, NR);
    // launch 9: rgcn layer 2 GEMM
    gemm_mma<false, false><<<gm, 256>>>(B, 384, Wt_cat, 384, b_rgcn, A, 384, N,
                                        384, 0, nullptr, nullptr, nullptr,
                                        nullptr, nullptr, nullptr, 0, nullptr,
                                        nullptr, nullptr, 0);
    // launch 10: head
    gemm_mma<true, false><<<gm, 256>>>(A, 384, Wt_o1, 128, b_o1, nullptr, 384,
                                       N, 128, 1, W_o2, b_o2, (float*)d_out,
                                       nullptr, nullptr, nullptr, 0, nullptr,
                                       nullptr, nullptr, 0);
}

// round 17
// speedup vs baseline: 1.5262x; 1.0020x over previous
#include <cuda_runtime.h>
#include <cuda_bf16.h>
#include <cstdint>

// ---------------------------------------------------------------------------
// BotRGCN on GB300 — bf16 mma.sync (m16n8k16) pipeline.
//   rgcn(x) = [x | mean_0(x) | mean_1(x)] @ [W_root; W_rel0; W_rel1] + b
// R17: R16 (523.4us) + ONE change: CSR place phase batched x4 (4 edges'
// loads, then 4 independent atomics in flight, then 4 scattered stores) to
// break the serial atomic->store latency chain (~45us of the W_in launch).
// ---------------------------------------------------------------------------

#define MAXN 100000
#define MAXE 3200000
#define NRSEG (MAXN * 2)

__device__ __align__(256) __nv_bfloat16 g_A[(size_t)MAXN * 384];
__device__ __align__(256) __nv_bfloat16 g_B[(size_t)MAXN * 384];
__device__ __align__(256) __nv_bfloat16 g_Wt_des[32 * 768];
__device__ __align__(256) __nv_bfloat16 g_Wt_tweet[32 * 768];
__device__ __align__(256) __nv_bfloat16 g_Wt_prop[32 * 64];
__device__ __align__(256) __nv_bfloat16 g_Wt_in[128 * 128];
__device__ __align__(256) __nv_bfloat16 g_Wt_cat[128 * 384];
__device__ __align__(256) __nv_bfloat16 g_Wt_o1[128 * 128];
__device__ __align__(256) int g_perm[MAXE];
__device__ __align__(256) int g_seg_start[NRSEG];
// cnt | cursor | total : one contiguous region, zeroed by a single memset
__device__ __align__(256) int g_cntcur[2 * NRSEG + 1];

__device__ __forceinline__ uint32_t smem_u32(const void* p) {
    uint32_t a;
    asm("{ .reg .u64 t; cvta.to.shared.u64 t, %1; cvt.u32.u64 %0, t; }"
        : "=r"(a) : "l"(p));
    return a;
}

#define CP_ASYNC16(dst, src, srcbytes)                                        \
    asm volatile("cp.async.cg.shared.global [%0], [%1], 16, %2;"              \
                 :: "r"(dst), "l"(src), "r"(srcbytes))
#define CP_COMMIT() asm volatile("cp.async.commit_group;" ::: "memory")
#define CP_WAIT(n) asm volatile("cp.async.wait_group %0;" :: "n"(n) : "memory")

// ------------------------- segment offsets (unordered CSR) -----------------

__global__ void seg_offsets_kernel(const int* __restrict__ cnt,
                                   int* __restrict__ seg_start,
                                   int* __restrict__ total, int n) {
    __shared__ int s[1024];
    __shared__ int base;
    int idx = blockIdx.x * 1024 + threadIdx.x;
    int v = (idx < n) ? cnt[idx] : 0;
    s[threadIdx.x] = v;
    __syncthreads();
    for (int off = 1; off < 1024; off <<= 1) {
        int t = (threadIdx.x >= off) ? s[threadIdx.x - off] : 0;
        __syncthreads();
        s[threadIdx.x] += t;
        __syncthreads();
    }
    if (threadIdx.x == 1023) base = atomicAdd(total, s[1023]);
    __syncthreads();
    if (idx < n) seg_start[idx] = base + s[threadIdx.x] - v;
}

// ------------------------- Weight prep (single launch) ---------------------

__device__ __forceinline__ void tr_one(const float* in, __nv_bfloat16* out,
                                       int idx, int K, int Nw, int Kpad) {
    int n = idx / Kpad, k = idx % Kpad;
    out[idx] = (k < K) ? __float2bfloat16_rn(in[k * Nw + n])
                       : __float2bfloat16_rn(0.f);
}

#define PREP_TOTAL (24576 + 24576 + 2048 + 16384 + 16384 + 49152)

__global__ void prep_kernel(const float* __restrict__ W_des,
                            const float* __restrict__ W_tweet,
                            const float* __restrict__ W_prop,
                            const float* __restrict__ W_in,
                            const float* __restrict__ W_o1,
                            const float* __restrict__ W_root,
                            const float* __restrict__ W_rel,
                            __nv_bfloat16* __restrict__ Wt_des,
                            __nv_bfloat16* __restrict__ Wt_tweet,
                            __nv_bfloat16* __restrict__ Wt_prop,
                            __nv_bfloat16* __restrict__ Wt_in,
                            __nv_bfloat16* __restrict__ Wt_o1,
                            __nv_bfloat16* __restrict__ Wt_cat) {
    int idx = blockIdx.x * blockDim.x + threadIdx.x;
    if (idx < 24576) {
        tr_one(W_des, Wt_des, idx, 768, 32, 768);
    } else if ((idx -= 24576) < 24576) {
        tr_one(W_tweet, Wt_tweet, idx, 768, 32, 768);
    } else if ((idx -= 24576) < 2048) {
        tr_one(W_prop, Wt_prop, idx, 14, 32, 64);
    } else if ((idx -= 2048) < 16384) {
        tr_one(W_in, Wt_in, idx, 96, 128, 128);
    } else if ((idx -= 16384) < 16384) {
        tr_one(W_o1, Wt_o1, idx, 128, 128, 128);
    } else if ((idx -= 16384) < 49152) {
        int n = idx / 384, k = idx % 384;
        float v = (k < 128) ? W_root[k * 128 + n] : W_rel[(k - 128) * 128 + n];
        Wt_cat[idx] = __float2bfloat16_rn(v);
    }
}

// ------------------------- mma primitives ----------------------------------

#define LDMX4(r0, r1, r2, r3, addr)                                           \
    asm volatile("ldmatrix.sync.aligned.m8n8.x4.shared.b16 {%0,%1,%2,%3}, [%4];" \
                 : "=r"(r0), "=r"(r1), "=r"(r2), "=r"(r3) : "r"(addr))
#define LDMX2(r0, r1, addr)                                                   \
    asm volatile("ldmatrix.sync.aligned.m8n8.x2.shared.b16 {%0,%1}, [%2];"    \
                 : "=r"(r0), "=r"(r1) : "r"(addr))
#define MMA16816(c, a, b)                                                     \
    asm volatile(                                                             \
        "mma.sync.aligned.m16n8k16.row.col.f32.bf16.bf16.f32 "                \
        "{%0,%1,%2,%3}, {%4,%5,%6,%7}, {%8,%9}, {%0,%1,%2,%3};"               \
        : "+f"((c)[0]), "+f"((c)[1]), "+f"((c)[2]), "+f"((c)[3])              \
        : "r"((a)[0]), "r"((a)[1]), "r"((a)[2]), "r"((a)[3]),                 \
          "r"((b)[0]), "r"((b)[1]))

// ------------------------- fused encoder GEMM + edge count ------------------
// Blocks [0, ncnt): CSR count (grid-stride histogram).
// Blocks [ncnt, ncnt + 3*gm): encoder slices (des | tweet | prop).

__global__ void __launch_bounds__(128) gemm_enc3_count(
    const float* __restrict__ des, const float* __restrict__ tweet,
    const float* __restrict__ prop,
    const __nv_bfloat16* __restrict__ Wt_des,
    const __nv_bfloat16* __restrict__ Wt_tweet,
    const __nv_bfloat16* __restrict__ Wt_prop,
    const float* __restrict__ b_des, const float* __restrict__ b_tweet,
    const float* __restrict__ b_prop, __nv_bfloat16* __restrict__ Bout,
    int M, int gm,
    const int* __restrict__ dstE, const int* __restrict__ etE, int E,
    int* __restrict__ cnt, int ncnt) {
    if (blockIdx.x < (unsigned)ncnt) {
        for (int i = blockIdx.x * 128 + threadIdx.x; i < E; i += ncnt * 128)
            atomicAdd(&cnt[dstE[i] * 2 + etE[i]], 1);
        return;
    }
    const int flat = blockIdx.x - ncnt;
    const int bx = flat % gm, by = flat / gm;

    const float* A;
    const __nv_bfloat16* Wt;
    const float* bias;
    __nv_bfloat16* C;
    int lda, K, ldw;
    if (by == 0) {
        A = des; Wt = Wt_des; bias = b_des; C = Bout; lda = 768; K = 768; ldw = 768;
    } else if (by == 1) {
        A = tweet; Wt = Wt_tweet; bias = b_tweet; C = Bout + 32; lda = 768; K = 768; ldw = 768;
    } else {
        A = prop; Wt = Wt_prop; bias = b_prop; C = Bout + 64; lda = 14; K = 14; ldw = 64;
    }
    const int ldc = 384;

    constexpr int STR = 40;
    __shared__ __nv_bfloat16 sA[128 * STR];
    __shared__ __nv_bfloat16 sB[32 * STR];

    const int tid = threadIdx.x;
    const int wid = tid >> 5, lane = tid & 31;
    const int row0 = bx * 128;
    const uint32_t baseA = smem_u32(sA);
    const uint32_t baseB = smem_u32(sB);

    float acc[2][4][4];
#pragma unroll
    for (int i = 0; i < 2; i++)
#pragma unroll
        for (int j = 0; j < 4; j++)
#pragma unroll
            for (int q = 0; q < 4; q++) acc[i][j][q] = 0.f;

    uint32_t aAddr[2];
#pragma unroll
    for (int i = 0; i < 2; i++)
        aAddr[i] = baseA + (uint32_t)(((wid * 32 + i * 16 + (lane & 15)) * STR +
                                       ((lane >> 4) * 8)) * 2);
    uint32_t bAddr[4];
#pragma unroll
    for (int j = 0; j < 4; j++)
        bAddr[j] = baseB + (uint32_t)(((j * 8 + (lane & 7)) * STR +
                                       (((lane >> 3) & 1) * 8)) * 2);

    const int nchunks = (K + 31) >> 5;
    for (int c = 0; c < nchunks; c++) {
        const int k0 = c << 5;
#pragma unroll 2
        for (int idx = tid; idx < 128 * 4; idx += 128) {
            int r = idx >> 2, g = idx & 3;
            int gr = row0 + r, gc0 = k0 + g * 8;
            uint4 val;
            if (gr < M && gc0 + 7 < K && (lda & 3) == 0) {
                const float4* p = (const float4*)(A + (size_t)gr * lda + gc0);
                float4 v0 = p[0], v1 = p[1];
                __nv_bfloat162 h0 = __floats2bfloat162_rn(v0.x, v0.y);
                __nv_bfloat162 h1 = __floats2bfloat162_rn(v0.z, v0.w);
                __nv_bfloat162 h2 = __floats2bfloat162_rn(v1.x, v1.y);
                __nv_bfloat162 h3 = __floats2bfloat162_rn(v1.z, v1.w);
                val.x = *(uint32_t*)&h0; val.y = *(uint32_t*)&h1;
                val.z = *(uint32_t*)&h2; val.w = *(uint32_t*)&h3;
            } else {
                float v[8];
#pragma unroll
                for (int e = 0; e < 8; e++) {
                    int gc = gc0 + e;
                    v[e] = (gr < M && gc < K) ? A[(size_t)gr * lda + gc] : 0.f;
                }
                __nv_bfloat162 h0 = __floats2bfloat162_rn(v[0], v[1]);
                __nv_bfloat162 h1 = __floats2bfloat162_rn(v[2], v[3]);
                __nv_bfloat162 h2 = __floats2bfloat162_rn(v[4], v[5]);
                __nv_bfloat162 h3 = __floats2bfloat162_rn(v[6], v[7]);
                val.x = *(uint32_t*)&h0; val.y = *(uint32_t*)&h1;
                val.z = *(uint32_t*)&h2; val.w = *(uint32_t*)&h3;
            }
            *(uint4*)(sA + r * STR + g * 8) = val;
        }
        {
            int n = tid >> 2, g = tid & 3;
            uint4 val = *(const uint4*)(Wt + (size_t)n * ldw + k0 + g * 8);
            *(uint4*)(sB + n * STR + g * 8) = val;
        }
        __syncthreads();

#pragma unroll
        for (int s = 0; s < 2; s++) {
            uint32_t bfr[4][2];
#pragma unroll
            for (int j = 0; j < 4; j++)
                LDMX2(bfr[j][0], bfr[j][1], bAddr[j] + s * 32);
#pragma unroll
            for (int i = 0; i < 2; i++) {
                uint32_t afr[4];
                LDMX4(afr[0], afr[1], afr[2], afr[3], aAddr[i] + s * 32);
#pragma unroll
                for (int j = 0; j < 4; j++) MMA16816(acc[i][j], afr, bfr[j]);
            }
        }
        __syncthreads();
    }

    const int qrow = lane >> 2, qcol = (lane & 3) * 2;
#pragma unroll
    for (int i = 0; i < 2; i++) {
#pragma unroll
        for (int j = 0; j < 4; j++) {
            int gc = j * 8 + qcol;
            float b0 = bias[gc], b1 = bias[gc + 1];
            int gr0 = row0 + wid * 32 + i * 16 + qrow;
            float v0 = acc[i][j][0] + b0, v1 = acc[i][j][1] + b1;
            float v2 = acc[i][j][2] + b0, v3 = acc[i][j][3] + b1;
            v0 = (v0 >= 0.f) ? v0 : 0.01f * v0;
            v1 = (v1 >= 0.f) ? v1 : 0.01f * v1;
            v2 = (v2 >= 0.f) ? v2 : 0.01f * v2;
            v3 = (v3 >= 0.f) ? v3 : 0.01f * v3;
            if (gr0 < M) {
                __nv_bfloat162 h = __floats2bfloat162_rn(v0, v1);
                *(uint32_t*)(C + (size_t)gr0 * ldc + gc) = *(uint32_t*)&h;
            }
            if (gr0 + 8 < M) {
                __nv_bfloat162 h = __floats2bfloat162_rn(v2, v3);
                *(uint32_t*)(C + (size_t)(gr0 + 8) * ldc + gc) = *(uint32_t*)&h;
            }
        }
    }
}

// ------------------------- main GEMM (bf16 A, cp.async 3-stage) ------------
// C[M,128](bf16, ldc) = act( A[M,K](bf16) @ Wt[128,K]^T + bias )
// BM=128, BN=128, BK=32; 8 warps (4x2), warp tile 32x64; triple-buffered.
// HEAD: softmax(lrelu(acc+bias) @ W_o2 + b_o2) -> fp32 [M,2].
// PLACE: blocks [0, nplace) run CSR place (x4-batched: loads, atomics,
// stores in separate phases so 4 atomic chains overlap).

template <bool HEAD, bool PLACE>
__global__ void __launch_bounds__(256) gemm_mma(
    const __nv_bfloat16* __restrict__ Aptr, int lda,
    const __nv_bfloat16* __restrict__ Wt, int ldw,
    const float* __restrict__ bias, __nv_bfloat16* __restrict__ C, int ldc,
    int M, int K, int act,
    const float* __restrict__ W_o2, const float* __restrict__ b_o2,
    float* __restrict__ outp,
    const int* __restrict__ srcE, const int* __restrict__ dstE,
    const int* __restrict__ etE, int E, const int* __restrict__ seg_start,
    int* __restrict__ cursor, int* __restrict__ perm, int nplace) {
    if (PLACE) {
        if (blockIdx.x < (unsigned)nplace) {
            const int stride = nplace * 256;
            int i = blockIdx.x * 256 + threadIdx.x;
            for (; i + 3 * stride < E; i += 4 * stride) {
                int seg[4], srcv[4], pos[4];
#pragma unroll
                for (int u = 0; u < 4; u++) {
                    int j = i + u * stride;
                    seg[u] = dstE[j] * 2 + etE[j];
                    srcv[u] = srcE[j];
                }
#pragma unroll
                for (int u = 0; u < 4; u++)
                    pos[u] = atomicAdd(&cursor[seg[u]], 1);
#pragma unroll
                for (int u = 0; u < 4; u++)
                    perm[seg_start[seg[u]] + pos[u]] = srcv[u];
            }
            for (; i < E; i += stride) {
                int seg = dstE[i] * 2 + etE[i];
                int p = atomicAdd(&cursor[seg], 1);
                perm[seg_start[seg] + p] = srcE[i];
            }
            return;
        }
    }
    const int bx = PLACE ? (blockIdx.x - nplace) : blockIdx.x;

    constexpr int BN = 128;
    constexpr int THREADS = 256;
    constexpr int WN = 64;
    constexpr int NATOMS = 8;
    constexpr int STR = 40;
    constexpr int STAGES = 3;
    constexpr uint32_t ABUF = 128 * STR * 2;  // bytes per buffer (A and B equal)

    __shared__ __nv_bfloat16 smem[(STAGES * 128 + STAGES * BN) * STR];

    const int tid = threadIdx.x;
    const int wid = tid >> 5, lane = tid & 31;
    const int wm = wid & 3, wn = wid >> 2;
    const int row0 = bx * 128;
    const uint32_t base = smem_u32(smem);
    const uint32_t baseA = base;                   // A0..A2
    const uint32_t baseB = base + STAGES * ABUF;   // B0..B2

    float acc[2][NATOMS][4];
#pragma unroll
    for (int i = 0; i < 2; i++)
#pragma unroll
        for (int j = 0; j < NATOMS; j++)
#pragma unroll
            for (int q = 0; q < 4; q++) acc[i][j][q] = 0.f;

    uint32_t aAddr[2];
#pragma unroll
    for (int i = 0; i < 2; i++)
        aAddr[i] = baseA + (uint32_t)(((wm * 32 + i * 16 + (lane & 15)) * STR +
                                       ((lane >> 4) * 8)) * 2);
    uint32_t bAddr[NATOMS];
#pragma unroll
    for (int j = 0; j < NATOMS; j++)
        bAddr[j] = baseB + (uint32_t)(((wn * WN + j * 8 + (lane & 7)) * STR +
                                       (((lane >> 3) & 1) * 8)) * 2);

    const int nchunks = (K + 31) >> 5;

    auto issue = [&](int c) {
        const int k0 = c << 5;
        const uint32_t st = (uint32_t)(c % STAGES);
        const uint32_t dA = baseA + st * ABUF;
        const uint32_t dB = baseB + st * ABUF;
#pragma unroll
        for (int it = 0; it < 2; it++) {
            int idx = tid + it * THREADS;   // 0..511
            int r = idx >> 2, g = idx & 3;
            int gr = row0 + r;
            int ok = (gr < M) ? 16 : 0;
            const __nv_bfloat16* src =
                Aptr + (size_t)(ok ? gr : 0) * lda + k0 + g * 8;
            CP_ASYNC16(dA + (uint32_t)((r * STR + g * 8) * 2), src, ok);
        }
#pragma unroll
        for (int it = 0; it < 2; it++) {
            int idx = tid + it * THREADS;
            int r = idx >> 2, g = idx & 3;
            const __nv_bfloat16* src = Wt + (size_t)r * ldw + k0 + g * 8;
            CP_ASYNC16(dB + (uint32_t)((r * STR + g * 8) * 2), src, 16);
        }
        CP_COMMIT();
    };

    issue(0);
    if (nchunks > 1) issue(1);
    for (int c = 0; c < nchunks; c++) {
        if (c + 2 < nchunks) {
            issue(c + 2);
            CP_WAIT(2);
        } else if (c + 1 < nchunks) {
            CP_WAIT(1);
        } else {
            CP_WAIT(0);
        }
        __syncthreads();

        const uint32_t boff = (uint32_t)(c % STAGES) * ABUF;
#pragma unroll
        for (int s = 0; s < 2; s++) {
            uint32_t bfr[NATOMS][2];
#pragma unroll
            for (int j = 0; j < NATOMS; j++)
                LDMX2(bfr[j][0], bfr[j][1], bAddr[j] + boff + s * 32);
#pragma unroll
            for (int i = 0; i < 2; i++) {
                uint32_t afr[4];
                LDMX4(afr[0], afr[1], afr[2], afr[3], aAddr[i] + boff + s * 32);
#pragma unroll
                for (int j = 0; j < NATOMS; j++) MMA16816(acc[i][j], afr, bfr[j]);
            }
        }
        __syncthreads();
    }

    const int qrow = lane >> 2, qcol = (lane & 3) * 2;

    if (!HEAD) {
#pragma unroll
        for (int i = 0; i < 2; i++) {
#pragma unroll
            for (int j = 0; j < NATOMS; j++) {
                int gc = wn * WN + j * 8 + qcol;
                float b0 = bias[gc], b1 = bias[gc + 1];
                int gr0 = row0 + wm * 32 + i * 16 + qrow;
                float v0 = acc[i][j][0] + b0, v1 = acc[i][j][1] + b1;
                float v2 = acc[i][j][2] + b0, v3 = acc[i][j][3] + b1;
                if (act) {
                    v0 = (v0 >= 0.f) ? v0 : 0.01f * v0;
                    v1 = (v1 >= 0.f) ? v1 : 0.01f * v1;
                    v2 = (v2 >= 0.f) ? v2 : 0.01f * v2;
                    v3 = (v3 >= 0.f) ? v3 : 0.01f * v3;
                }
                if (gr0 < M) {
                    __nv_bfloat162 h = __floats2bfloat162_rn(v0, v1);
                    *(uint32_t*)(C + (size_t)gr0 * ldc + gc) = *(uint32_t*)&h;
                }
                if (gr0 + 8 < M) {
                    __nv_bfloat162 h = __floats2bfloat162_rn(v2, v3);
                    *(uint32_t*)(C + (size_t)(gr0 + 8) * ldc + gc) = *(uint32_t*)&h;
                }
            }
        }
    } else {
        __shared__ float sred[2][128][2];
        float p0[4] = {0.f, 0.f, 0.f, 0.f};
        float p1[4] = {0.f, 0.f, 0.f, 0.f};
#pragma unroll
        for (int i = 0; i < 2; i++) {
#pragma unroll
            for (int j = 0; j < NATOMS; j++) {
                int gc = wn * WN + j * 8 + qcol;
                float b0 = bias[gc], b1 = bias[gc + 1];
                float v0 = acc[i][j][0] + b0, v1 = acc[i][j][1] + b1;
                float v2 = acc[i][j][2] + b0, v3 = acc[i][j][3] + b1;
                v0 = (v0 >= 0.f) ? v0 : 0.01f * v0;
                v1 = (v1 >= 0.f) ? v1 : 0.01f * v1;
                v2 = (v2 >= 0.f) ? v2 : 0.01f * v2;
                v3 = (v3 >= 0.f) ? v3 : 0.01f * v3;
                float w00 = W_o2[gc * 2], w01 = W_o2[gc * 2 + 1];
                float w10 = W_o2[(gc + 1) * 2], w11 = W_o2[(gc + 1) * 2 + 1];
                p0[i * 2 + 0] += v0 * w00 + v1 * w10;
                p1[i * 2 + 0] += v0 * w01 + v1 * w11;
                p0[i * 2 + 1] += v2 * w00 + v3 * w10;
                p1[i * 2 + 1] += v2 * w01 + v3 * w11;
            }
        }
#pragma unroll
        for (int off = 1; off <= 2; off <<= 1) {
#pragma unroll
            for (int k = 0; k < 4; k++) {
                p0[k] += __shfl_xor_sync(0xFFFFFFFFu, p0[k], off);
                p1[k] += __shfl_xor_sync(0xFFFFFFFFu, p1[k], off);
            }
        }
        if ((lane & 3) == 0) {
#pragma unroll
            for (int k = 0; k < 4; k++) {
                int row = wm * 32 + (k >> 1) * 16 + qrow + (k & 1) * 8;
                sred[wn][row][0] = p0[k];
                sred[wn][row][1] = p1[k];
            }
        }
        __syncthreads();
        if (tid < 128) {
            int gr = row0 + tid;
            if (gr < M) {
                float l0 = b_o2[0] + sred[0][tid][0] + sred[1][tid][0];
                float l1 = b_o2[1] + sred[0][tid][1] + sred[1][tid][1];
                float m = fmaxf(l0, l1);
                float e0 = __expf(l0 - m), e1 = __expf(l1 - m);
                float inv = 1.f / (e0 + e1);
                outp[(size_t)gr * 2] = e0 * inv;
                outp[(size_t)gr * 2 + 1] = e1 * inv;
            }
        }
    }
}

// ------------------------- Aggregation (bf16, warp/segment — R10 exact) ----

__global__ void aggregate_kernel(__nv_bfloat16* __restrict__ buf,
                                 const int* __restrict__ seg_start,
                                 const int* __restrict__ cnt,
                                 const int* __restrict__ perm, int NR) {
    int w = blockIdx.x * (blockDim.x >> 5) + (threadIdx.x >> 5);
    if (w >= NR) return;
    int lane = threadIdx.x & 31;
    int start = seg_start[w];
    int deg = cnt[w];
    int end = start + deg;
    float a0 = 0.f, a1 = 0.f, a2 = 0.f, a3 = 0.f;
    int e = start;
    for (; e + 3 < end; e += 4) {
        int s0 = perm[e], s1 = perm[e + 1], s2 = perm[e + 2], s3 = perm[e + 3];
        uint2 v0 = *(const uint2*)(buf + (size_t)s0 * 384 + lane * 4);
        uint2 v1 = *(const uint2*)(buf + (size_t)s1 * 384 + lane * 4);
        uint2 v2 = *(const uint2*)(buf + (size_t)s2 * 384 + lane * 4);
        uint2 v3 = *(const uint2*)(buf + (size_t)s3 * 384 + lane * 4);
#define ACCUM(v)                                                              \
        {                                                                     \
            float2 f0 = __bfloat1622float2(*(__nv_bfloat162*)&(v).x);         \
            float2 f1 = __bfloat1622float2(*(__nv_bfloat162*)&(v).y);         \
            a0 += f0.x; a1 += f0.y; a2 += f1.x; a3 += f1.y;                   \
        }
        ACCUM(v0) ACCUM(v1) ACCUM(v2) ACCUM(v3)
    }
    for (; e < end; e++) {
        int s = perm[e];
        uint2 v = *(const uint2*)(buf + (size_t)s * 384 + lane * 4);
        ACCUM(v)
    }
#undef ACCUM
    float inv = 1.f / (float)max(deg, 1);
    __nv_bfloat162 h0 = __floats2bfloat162_rn(a0 * inv, a1 * inv);
    __nv_bfloat162 h1 = __floats2bfloat162_rn(a2 * inv, a3 * inv);
    uint2 outv;
    outv.x = *(uint32_t*)&h0;
    outv.y = *(uint32_t*)&h1;
    int node = w >> 1, r = w & 1;
    *(uint2*)(buf + (size_t)node * 384 + 128 + r * 128 + lane * 4) = outv;
}

// ------------------------- Launch ------------------------------------------

extern "C" void kernel_launch(void* const* d_in, const int* in_sizes, int n_in,
                              void* d_out, int out_size) {
    const float* des     = (const float*)d_in[0];
    const float* tweet   = (const float*)d_in[1];
    const float* prop    = (const float*)d_in[2];
    const int*   eidx    = (const int*)d_in[3];
    const int*   etype   = (const int*)d_in[4];
    const float* W_des   = (const float*)d_in[5];
    const float* b_des   = (const float*)d_in[6];
    const float* W_tweet = (const float*)d_in[7];
    const float* b_tweet = (const float*)d_in[8];
    const float* W_prop  = (const float*)d_in[9];
    const float* b_prop  = (const float*)d_in[10];
    const float* W_in    = (const float*)d_in[11];
    const float* b_in    = (const float*)d_in[12];
    const float* W_rel   = (const float*)d_in[13];
    const float* W_root  = (const float*)d_in[14];
    const float* b_rgcn  = (const float*)d_in[15];
    const float* W_o1    = (const float*)d_in[16];
    const float* b_o1    = (const float*)d_in[17];
    const float* W_o2    = (const float*)d_in[18];
    const float* b_o2    = (const float*)d_in[19];

    const int N = in_sizes[0] / 768;
    const int E = in_sizes[4];
    const int NR = N * 2;
    const int* src = eidx;
    const int* dst = eidx + E;

    __nv_bfloat16 *A, *B, *Wt_des, *Wt_tweet, *Wt_prop, *Wt_in, *Wt_cat, *Wt_o1;
    cudaGetSymbolAddress((void**)&A, g_A);
    cudaGetSymbolAddress((void**)&B, g_B);
    cudaGetSymbolAddress((void**)&Wt_des, g_Wt_des);
    cudaGetSymbolAddress((void**)&Wt_tweet, g_Wt_tweet);
    cudaGetSymbolAddress((void**)&Wt_prop, g_Wt_prop);
    cudaGetSymbolAddress((void**)&Wt_in, g_Wt_in);
    cudaGetSymbolAddress((void**)&Wt_cat, g_Wt_cat);
    cudaGetSymbolAddress((void**)&Wt_o1, g_Wt_o1);
    int *perm, *seg_start, *cntcur;
    cudaGetSymbolAddress((void**)&perm, g_perm);
    cudaGetSymbolAddress((void**)&seg_start, g_seg_start);
    cudaGetSymbolAddress((void**)&cntcur, g_cntcur);
    int* cnt = cntcur;
    int* cursor = cntcur + NRSEG;
    int* total = cntcur + 2 * NRSEG;

    const int gm = (N + 127) / 128;
    const int ncnt = 2048;
    const int nplace = 1024;

    // launch 1: zero cnt + cursor + total in one memset
    cudaMemsetAsync(cntcur, 0, (size_t)(2 * NRSEG + 1) * sizeof(int));
    // launch 2: weight prep
    prep_kernel<<<(PREP_TOTAL + 255) / 256, 256>>>(
        W_des, W_tweet, W_prop, W_in, W_o1, W_root, W_rel, Wt_des, Wt_tweet,
        Wt_prop, Wt_in, Wt_o1, Wt_cat);
    // launch 3: encoders + CSR count
    gemm_enc3_count<<<ncnt + gm * 3, 128>>>(des, tweet, prop, Wt_des, Wt_tweet,
                                            Wt_prop, b_des, b_tweet, b_prop, B,
                                            N, gm, dst, etype, E, cnt, ncnt);
    // launch 4: segment offsets (unordered CSR)
    seg_offsets_kernel<<<(NR + 1023) / 1024, 1024>>>(cnt, seg_start, total, NR);
    // launch 5 (ncu sample): cat96 @ W_in -> A cols 0..127, fused with place
    gemm_mma<false, true><<<nplace + gm, 256>>>(
        B, 384, Wt_in, 128, b_in, A, 384, N, 96, 1, nullptr, nullptr, nullptr,
        src, dst, etype, E, seg_start, cursor, perm, nplace);
    // launch 6: aggregate layer 1
    aggregate_kernel<<<(NR + 7) / 8, 256>>>(A, seg_start, cnt, perm, NR);
    // launch 7: rgcn layer 1 GEMM
    gemm_mma<false, false><<<gm, 256>>>(A, 384, Wt_cat, 384, b_rgcn, B, 384, N,
                                        384, 0, nullptr, nullptr, nullptr,
                                        nullptr, nullptr, nullptr, 0, nullptr,
                                        nullptr, nullptr, 0);
    // launch 8: aggregate layer 2
    aggregate_kernel<<<(NR + 7) / 8, 256>>>(B, seg_start, cnt, perm, NR);
    // launch 9: rgcn layer 2 GEMM
    gemm_mma<false, false><<<gm, 256>>>(B, 384, Wt_cat, 384, b_rgcn, A, 384, N,
                                        384, 0, nullptr, nullptr, nullptr,
                                        nullptr, nullptr, nullptr, 0, nullptr,
                                        nullptr, nullptr, 0);
    // launch 10: head
    gemm_mma<true, false><<<gm, 256>>>(A, 384, Wt_o1, 128, b_o1, nullptr, 384,
                                       N, 128, 1, W_o2, b_o2, (float*)d_out,
                                       nullptr, nullptr, nullptr, 0, nullptr,
                                       nullptr, nullptr, 0);
}